// round 4
// baseline (speedup 1.0000x reference)
#include <cuda_runtime.h>
#include <cuda_fp16.h>
#include <math.h>

#define NN 50000
#define NE 1600000
#define FIN 128
#define HID 160
#define NG 512
#define NC 2
#define BN_EPS 1e-5f

// ---------------- scratch (static __device__, no allocs) ----------------
__device__ __align__(16) __half g_hs[NN * HID];    // fp16 scaled linear output (gather source)
__device__ __align__(16) __half g_feat[NN * HID];  // fp16 layer output features
__device__ float g_inv[NN];                        // 1/sqrt(deg)
__device__ int   g_indeg[NN];
__device__ int   g_rowptr[NN + 1];
__device__ int   g_cursor[NN];
__device__ int   g_colidx[NE];
__device__ int   g_bsums[128];
__device__ int   g_gcnt[NG];
__device__ int   g_goff[NG + 1];
__device__ float g_pooled[NG * HID];

// ---------------- f32x2 helpers ----------------
__device__ __forceinline__ unsigned long long f2_fma(unsigned long long a,
                                                     unsigned long long b,
                                                     unsigned long long c) {
    unsigned long long d;
    asm("fma.rn.f32x2 %0, %1, %2, %3;" : "=l"(d) : "l"(a), "l"(b), "l"(c));
    return d;
}
__device__ __forceinline__ unsigned long long f2_dup(float a) {
    unsigned long long d;
    asm("mov.b64 %0, {%1, %1};" : "=l"(d) : "f"(a));
    return d;
}
union F2U { float2 f2; unsigned long long u; };
__device__ __forceinline__ unsigned long long ld2(const float* p) {
    F2U t; t.f2 = *reinterpret_cast<const float2*>(p); return t.u;
}

// ---------------- build: count indeg + graph-node counts ----------------
__global__ void k_count2(const int* __restrict__ dst, const int* __restrict__ batch) {
    int stride = gridDim.x * blockDim.x;
    int t0 = blockIdx.x * blockDim.x + threadIdx.x;
    for (int e = t0; e < NE; e += stride)
        atomicAdd(&g_indeg[dst[e]], 1);
    for (int i = t0; i < NN; i += stride)
        atomicAdd(&g_gcnt[batch[i]], 1);
}

// ---------------- exclusive scan of indeg -> rowptr (pass 1) ----------------
__global__ void k_scan1() {   // grid: 98 blocks x 512
    __shared__ int sh[512];
    int i = blockIdx.x * 512 + threadIdx.x;
    int v = (i < NN) ? g_indeg[i] : 0;
    sh[threadIdx.x] = v;
    __syncthreads();
    for (int off = 1; off < 512; off <<= 1) {
        int t = (threadIdx.x >= off) ? sh[threadIdx.x - off] : 0;
        __syncthreads();
        sh[threadIdx.x] += t;
        __syncthreads();
    }
    if (i < NN) g_rowptr[i] = sh[threadIdx.x] - v;  // exclusive within block
    if (threadIdx.x == 511) g_bsums[blockIdx.x] = sh[511];
}

// ---------------- block-sums scan (parallel) + graph-offset scan ----------------
__global__ void k_scan2g(int nb) {   // 1 block x 512
    __shared__ int sb[128];
    __shared__ int sg[512];
    int x = threadIdx.x;
    int vb = 0;
    if (x < 128) { vb = (x < nb) ? g_bsums[x] : 0; sb[x] = vb; }
    __syncthreads();
    for (int off = 1; off < 128; off <<= 1) {
        int t = (x < 128 && x >= off) ? sb[x - off] : 0;
        __syncthreads();
        if (x < 128) sb[x] += t;
        __syncthreads();
    }
    if (x < nb) g_bsums[x] = sb[x] - vb;   // exclusive
    int vg = g_gcnt[x];
    sg[x] = vg;
    __syncthreads();
    for (int off = 1; off < 512; off <<= 1) {
        int t = (x >= off) ? sg[x - off] : 0;
        __syncthreads();
        sg[x] += t;
        __syncthreads();
    }
    g_goff[x] = sg[x] - vg;
    if (x == 511) g_goff[NG] = sg[511];
}

__global__ void k_scan3() {
    int i = blockIdx.x * blockDim.x + threadIdx.x;
    if (i < NN) {
        int r = g_rowptr[i] + g_bsums[i >> 9];
        g_rowptr[i] = r;
        g_cursor[i] = r;
        g_inv[i] = rsqrtf((float)g_indeg[i] + 1.0f);   // deg = indeg + self loop
    }
    if (i == 0) g_rowptr[NN] = NE;
}

__global__ void k_scatter(const int* __restrict__ src, const int* __restrict__ dst) {
    for (int e = blockIdx.x * blockDim.x + threadIdx.x; e < NE; e += gridDim.x * blockDim.x) {
        int p = atomicAdd(&g_cursor[dst[e]], 1);
        g_colidx[p] = src[e];
    }
}

// ---------------- GEMM: g_hs = fp16( (X @ W) * inv[row] ) ----------------
// Block tile 128 x 160, 256 threads, per-thread 8 rows x 5 col-pairs, f32x2 FMA.
// Two variants for the A-tile load (fp32 input vs fp16 input).
template <bool A_HALF>
__global__ __launch_bounds__(256) void k_gemm(const float* __restrict__ Xf,
                                              const __half* __restrict__ Xh,
                                              const float* __restrict__ W,
                                              int M, int K) {
    __shared__ __align__(16) float As[32][128];   // k-major: [k][row]
    __shared__ __align__(16) float Bs[32][160];   // [k][col]
    const int tid = threadIdx.x;
    const int tx = tid & 15;
    const int ty = tid >> 4;
    const int rowBase = blockIdx.x * 128;

    unsigned long long acc[8][5];
#pragma unroll
    for (int q = 0; q < 8; q++)
#pragma unroll
        for (int p = 0; p < 5; p++) acc[q][p] = 0ull;

    for (int k0 = 0; k0 < K; k0 += 32) {
        if (A_HALF) {
#pragma unroll
            for (int i = 0; i < 2; i++) {
                int idx = tid + i * 256;          // < 512
                int row = idx & 127;
                int k8 = (idx >> 7) << 3;         // 0,8,16,24
                int gr = rowBase + row;
                uint4 v = make_uint4(0u, 0u, 0u, 0u);
                if (gr < M)
                    v = *reinterpret_cast<const uint4*>(Xh + (size_t)gr * K + k0 + k8);
                const __half2* hp = reinterpret_cast<const __half2*>(&v);
#pragma unroll
                for (int j = 0; j < 4; j++) {
                    float2 f = __half22float2(hp[j]);
                    As[k8 + 2 * j][row] = f.x;
                    As[k8 + 2 * j + 1][row] = f.y;
                }
            }
        } else {
#pragma unroll
            for (int i = 0; i < 4; i++) {
                int idx = tid + i * 256;          // < 1024
                int row = idx & 127;
                int k = (idx >> 7) << 2;          // 0,4,...,28
                int gr = rowBase + row;
                float4 v = make_float4(0.f, 0.f, 0.f, 0.f);
                if (gr < M) v = *reinterpret_cast<const float4*>(Xf + (size_t)gr * K + k0 + k);
                As[k + 0][row] = v.x;
                As[k + 1][row] = v.y;
                As[k + 2][row] = v.z;
                As[k + 3][row] = v.w;
            }
        }
#pragma unroll
        for (int i = 0; i < 5; i++) {
            int idx = tid + i * 256;          // < 1280
            int k = idx / 40;
            int c4 = idx % 40;
            *reinterpret_cast<float4*>(&Bs[k][c4 * 4]) =
                *reinterpret_cast<const float4*>(W + (size_t)(k0 + k) * HID + c4 * 4);
        }
        __syncthreads();
#pragma unroll
        for (int kk = 0; kk < 32; kk++) {
            float4 a0 = *reinterpret_cast<const float4*>(&As[kk][ty * 8]);
            float4 a1 = *reinterpret_cast<const float4*>(&As[kk][ty * 8 + 4]);
            unsigned long long pa[8];
            pa[0] = f2_dup(a0.x); pa[1] = f2_dup(a0.y);
            pa[2] = f2_dup(a0.z); pa[3] = f2_dup(a0.w);
            pa[4] = f2_dup(a1.x); pa[5] = f2_dup(a1.y);
            pa[6] = f2_dup(a1.z); pa[7] = f2_dup(a1.w);
            unsigned long long b[5];
#pragma unroll
            for (int p = 0; p < 5; p++) b[p] = ld2(&Bs[kk][32 * p + 2 * tx]);
#pragma unroll
            for (int q = 0; q < 8; q++)
#pragma unroll
                for (int p = 0; p < 5; p++) acc[q][p] = f2_fma(pa[q], b[p], acc[q][p]);
        }
        __syncthreads();
    }
    // epilogue: scale by inv[row], convert to fp16, store
#pragma unroll
    for (int q = 0; q < 8; q++) {
        int gr = rowBase + ty * 8 + q;
        if (gr < M) {
            float s = g_inv[gr];
            __half* dstp = g_hs + (size_t)gr * HID;
#pragma unroll
            for (int p = 0; p < 5; p++) {
                F2U t; t.u = acc[q][p];
                t.f2.x *= s; t.f2.y *= s;
                *reinterpret_cast<__half2*>(dstp + 32 * p + 2 * tx) = __float22half2_rn(t.f2);
            }
        }
    }
}

// ---------------- Aggregate + bias + BN + ReLU (fp16 rows, fp32 accum) ----------------
// Row layout per warp: lane owns halves [4*lane .. 4*lane+3] (one uint2 load),
// lanes 0..15 additionally own halves [128+2*lane, +1] (one uint load).
__global__ __launch_bounds__(256) void k_agg(const float* __restrict__ bias,
                                             const float* __restrict__ gam,
                                             const float* __restrict__ bet,
                                             const float* __restrict__ mean,
                                             const float* __restrict__ var) {
    int d = (blockIdx.x * blockDim.x + threadIdx.x) >> 5;
    int lane = threadIdx.x & 31;
    if (d >= NN) return;
    bool tail = lane < 16;

    const __half* hr = g_hs + (size_t)d * HID;

    // self-loop init
    float a0, a1, a2, a3, t0 = 0.f, t1 = 0.f;
    {
        uint2 v = *reinterpret_cast<const uint2*>(hr + 4 * lane);
        const __half2* hp = reinterpret_cast<const __half2*>(&v);
        float2 f0 = __half22float2(hp[0]);
        float2 f1 = __half22float2(hp[1]);
        a0 = f0.x; a1 = f0.y; a2 = f1.x; a3 = f1.y;
        if (tail) {
            __half2 hv = *reinterpret_cast<const __half2*>(hr + 128 + 2 * lane);
            float2 ft = __half22float2(hv);
            t0 = ft.x; t1 = ft.y;
        }
    }

    // hoisted BN constants
    int c = 4 * lane;
    int ct = 128 + 2 * lane;
    float idv = g_inv[d];
    float A0 = gam[c]     * rsqrtf(var[c]     + BN_EPS);
    float A1 = gam[c + 1] * rsqrtf(var[c + 1] + BN_EPS);
    float A2 = gam[c + 2] * rsqrtf(var[c + 2] + BN_EPS);
    float A3 = gam[c + 3] * rsqrtf(var[c + 3] + BN_EPS);
    float Q0 = (bias[c]     - mean[c])     * A0 + bet[c];
    float Q1 = (bias[c + 1] - mean[c + 1]) * A1 + bet[c + 1];
    float Q2 = (bias[c + 2] - mean[c + 2]) * A2 + bet[c + 2];
    float Q3 = (bias[c + 3] - mean[c + 3]) * A3 + bet[c + 3];
    float A4 = 0.f, A5 = 0.f, Q4 = 0.f, Q5 = 0.f;
    if (tail) {
        A4 = gam[ct]     * rsqrtf(var[ct]     + BN_EPS);
        A5 = gam[ct + 1] * rsqrtf(var[ct + 1] + BN_EPS);
        Q4 = (bias[ct]     - mean[ct])     * A4 + bet[ct];
        Q5 = (bias[ct + 1] - mean[ct + 1]) * A5 + bet[ct + 1];
    }

    int beg = g_rowptr[d], end = g_rowptr[d + 1];
    for (int e0 = beg; e0 < end; e0 += 32) {
        int n = min(32, end - e0);
        int myidx = (lane < n) ? g_colidx[e0 + lane] : 0;
        for (int t = 0; t < n; t++) {
            int s = __shfl_sync(0xffffffffu, myidx, t);
            const __half* r = g_hs + (size_t)s * HID;
            uint2 v = *reinterpret_cast<const uint2*>(r + 4 * lane);
            const __half2* hp = reinterpret_cast<const __half2*>(&v);
            float2 f0 = __half22float2(hp[0]);
            float2 f1 = __half22float2(hp[1]);
            a0 += f0.x; a1 += f0.y; a2 += f1.x; a3 += f1.y;
            if (tail) {
                __half2 hv = *reinterpret_cast<const __half2*>(r + 128 + 2 * lane);
                float2 ft = __half22float2(hv);
                t0 += ft.x; t1 += ft.y;
            }
        }
    }

    __half* o = g_feat + (size_t)d * HID;
    float2 y01, y23;
    y01.x = fmaxf(fmaf(a0, idv * A0, Q0), 0.f);
    y01.y = fmaxf(fmaf(a1, idv * A1, Q1), 0.f);
    y23.x = fmaxf(fmaf(a2, idv * A2, Q2), 0.f);
    y23.y = fmaxf(fmaf(a3, idv * A3, Q3), 0.f);
    uint2 ov;
    *reinterpret_cast<__half2*>(&ov.x) = __float22half2_rn(y01);
    *reinterpret_cast<__half2*>(&ov.y) = __float22half2_rn(y23);
    *reinterpret_cast<uint2*>(o + 4 * lane) = ov;
    if (tail) {
        float2 yt;
        yt.x = fmaxf(fmaf(t0, idv * A4, Q4), 0.f);
        yt.y = fmaxf(fmaf(t1, idv * A5, Q5), 0.f);
        *reinterpret_cast<__half2*>(o + 128 + 2 * lane) = __float22half2_rn(yt);
    }
}

// ---------------- mean pool per graph ----------------
__global__ void k_pool() {   // grid: NG blocks x 80 threads (2 cols/thread)
    int g = blockIdx.x;
    int j = threadIdx.x;
    int s0 = g_goff[g];
    int cnt = g_goff[g + 1] - s0;
    float sx = 0.f, sy = 0.f;
    for (int i = 0; i < cnt; i++) {
        __half2 hv = *reinterpret_cast<const __half2*>(g_feat + (size_t)(s0 + i) * HID + 2 * j);
        float2 f = __half22float2(hv);
        sx += f.x; sy += f.y;
    }
    float invc = 1.f / fmaxf((float)cnt, 1.f);
    g_pooled[g * HID + 2 * j] = sx * invc;
    g_pooled[g * HID + 2 * j + 1] = sy * invc;
}

// ---------------- MLP head ----------------
__global__ void k_head(const float* __restrict__ Wc1, const float* __restrict__ bc1,
                       const float* __restrict__ Wc2, const float* __restrict__ bc2,
                       float* __restrict__ out) {   // grid: NG blocks x 80 threads
    __shared__ float p[HID];
    __shared__ float z[80];
    int g = blockIdx.x;
    int j = threadIdx.x;
    p[j] = g_pooled[g * HID + j];
    p[j + 80] = g_pooled[g * HID + j + 80];
    __syncthreads();
    float s = bc1[j];
    for (int i = 0; i < HID; i++) s = fmaf(p[i], Wc1[i * 80 + j], s);
    z[j] = fmaxf(s, 0.f);
    __syncthreads();
    if (j < NC) {
        float o = bc2[j];
        for (int i = 0; i < 80; i++) o = fmaf(z[i], Wc2[i * NC + j], o);
        out[g * NC + j] = o;
    }
}

// ---------------- launch ----------------
extern "C" void kernel_launch(void* const* d_in, const int* in_sizes, int n_in,
                              void* d_out, int out_size) {
    const float* x   = (const float*)d_in[0];
    const int* ei    = (const int*)d_in[1];
    const int* batch = (const int*)d_in[2];
    const float* W1  = (const float*)d_in[3];
    const float* b1  = (const float*)d_in[4];
    const float* W2  = (const float*)d_in[5];
    const float* b2  = (const float*)d_in[6];
    const float* W3  = (const float*)d_in[7];
    const float* b3  = (const float*)d_in[8];
    const float* g1  = (const float*)d_in[9];
    const float* be1 = (const float*)d_in[10];
    const float* m1  = (const float*)d_in[11];
    const float* v1  = (const float*)d_in[12];
    const float* g2  = (const float*)d_in[13];
    const float* be2 = (const float*)d_in[14];
    const float* m2  = (const float*)d_in[15];
    const float* v2  = (const float*)d_in[16];
    const float* g3  = (const float*)d_in[17];
    const float* be3 = (const float*)d_in[18];
    const float* m3  = (const float*)d_in[19];
    const float* v3  = (const float*)d_in[20];
    const float* Wc1 = (const float*)d_in[21];
    const float* bc1 = (const float*)d_in[22];
    const float* Wc2 = (const float*)d_in[23];
    const float* bc2 = (const float*)d_in[24];
    const int* src = ei;
    const int* dst = ei + NE;
    float* out = (float*)d_out;

    __half* feat_ptr = nullptr;
    cudaGetSymbolAddress((void**)&feat_ptr, g_feat);
    void* indeg_ptr = nullptr;
    cudaGetSymbolAddress(&indeg_ptr, g_indeg);
    void* gcnt_ptr = nullptr;
    cudaGetSymbolAddress(&gcnt_ptr, g_gcnt);

    // ---- graph structure (rebuilt each call; deterministic work) ----
    cudaMemsetAsync(indeg_ptr, 0, NN * sizeof(int));
    cudaMemsetAsync(gcnt_ptr, 0, NG * sizeof(int));
    k_count2<<<2048, 256>>>(dst, batch);
    k_scan1<<<(NN + 511) / 512, 512>>>();
    k_scan2g<<<1, 512>>>((NN + 511) / 512);
    k_scan3<<<(NN + 255) / 256, 256>>>();
    k_scatter<<<2048, 256>>>(src, dst);

    const int gemm_blocks = (NN + 127) / 128;
    const int agg_blocks = (NN + 7) / 8;   // 8 warps per 256-thread block

    // layer 1 (fp32 A)
    k_gemm<false><<<gemm_blocks, 256>>>(x, nullptr, W1, NN, FIN);
    k_agg<<<agg_blocks, 256>>>(b1, g1, be1, m1, v1);
    // layer 2 (fp16 A)
    k_gemm<true><<<gemm_blocks, 256>>>(nullptr, feat_ptr, W2, NN, HID);
    k_agg<<<agg_blocks, 256>>>(b2, g2, be2, m2, v2);
    // layer 3 (fp16 A)
    k_gemm<true><<<gemm_blocks, 256>>>(nullptr, feat_ptr, W3, NN, HID);
    k_agg<<<agg_blocks, 256>>>(b3, g3, be3, m3, v3);

    // pool + head
    k_pool<<<NG, 80>>>();
    k_head<<<NG, 80>>>(Wc1, bc1, Wc2, bc2, out);
}

// round 5
// speedup vs baseline: 1.7405x; 1.7405x over previous
#include <cuda_runtime.h>
#include <math.h>

#define NN 50000
#define NE 1600000
#define FIN 128
#define HID 160
#define NG 512
#define NC 2
#define BN_EPS 1e-5f

// ---------------- scratch (static __device__, no allocs) ----------------
// bf16 raw storage (unsigned short), converted with ALU bit-ops (no F2F).
__device__ __align__(16) unsigned short g_hs[NN * HID];    // scaled linear output (gather source)
__device__ __align__(16) unsigned short g_feat[NN * HID];  // layer output features
__device__ float g_inv[NN];                                // 1/sqrt(deg)
__device__ int   g_indeg[NN];
__device__ int   g_rowptr[NN + 1];
__device__ int   g_cursor[NN];
__device__ int   g_colidx[NE];
__device__ int   g_bsums[128];
__device__ int   g_gcnt[NG];
__device__ int   g_goff[NG + 1];
__device__ float g_pooled[NG * HID];

// ---------------- helpers ----------------
__device__ __forceinline__ unsigned long long f2_fma(unsigned long long a,
                                                     unsigned long long b,
                                                     unsigned long long c) {
    unsigned long long d;
    asm("fma.rn.f32x2 %0, %1, %2, %3;" : "=l"(d) : "l"(a), "l"(b), "l"(c));
    return d;
}
__device__ __forceinline__ unsigned long long f2_dup(float a) {
    unsigned long long d;
    asm("mov.b64 %0, {%1, %1};" : "=l"(d) : "f"(a));
    return d;
}
union F2U { float2 f2; unsigned long long u; };
__device__ __forceinline__ unsigned long long ld2(const float* p) {
    F2U t; t.f2 = *reinterpret_cast<const float2*>(p); return t.u;
}
// bf16 pair (packed in uint) -> two floats, pure ALU
__device__ __forceinline__ float bflo(unsigned u) { return __uint_as_float(u << 16); }
__device__ __forceinline__ float bfhi(unsigned u) { return __uint_as_float(u & 0xffff0000u); }
// two floats -> packed bf16x2 (epilogue only)
__device__ __forceinline__ unsigned bfpack(float lo, float hi) {
    unsigned r;
    asm("cvt.rn.bf16x2.f32 %0, %1, %2;" : "=r"(r) : "f"(hi), "f"(lo));
    return r;
}

// ---------------- build: count indeg + graph-node counts ----------------
__global__ void k_count2(const int* __restrict__ dst, const int* __restrict__ batch) {
    int stride = gridDim.x * blockDim.x;
    int t0 = blockIdx.x * blockDim.x + threadIdx.x;
    for (int e = t0; e < NE; e += stride)
        atomicAdd(&g_indeg[dst[e]], 1);
    for (int i = t0; i < NN; i += stride)
        atomicAdd(&g_gcnt[batch[i]], 1);
}

// ---------------- exclusive scan of indeg -> rowptr (pass 1) ----------------
__global__ void k_scan1() {   // grid: 98 blocks x 512
    __shared__ int sh[512];
    int i = blockIdx.x * 512 + threadIdx.x;
    int v = (i < NN) ? g_indeg[i] : 0;
    sh[threadIdx.x] = v;
    __syncthreads();
    for (int off = 1; off < 512; off <<= 1) {
        int t = (threadIdx.x >= off) ? sh[threadIdx.x - off] : 0;
        __syncthreads();
        sh[threadIdx.x] += t;
        __syncthreads();
    }
    if (i < NN) g_rowptr[i] = sh[threadIdx.x] - v;  // exclusive within block
    if (threadIdx.x == 511) g_bsums[blockIdx.x] = sh[511];
}

// ---------------- block-sums scan (parallel) + graph-offset scan ----------------
__global__ void k_scan2g(int nb) {   // 1 block x 512
    __shared__ int sb[128];
    __shared__ int sg[512];
    int x = threadIdx.x;
    int vb = 0;
    if (x < 128) { vb = (x < nb) ? g_bsums[x] : 0; sb[x] = vb; }
    __syncthreads();
    for (int off = 1; off < 128; off <<= 1) {
        int t = (x < 128 && x >= off) ? sb[x - off] : 0;
        __syncthreads();
        if (x < 128) sb[x] += t;
        __syncthreads();
    }
    if (x < nb) g_bsums[x] = sb[x] - vb;   // exclusive
    int vg = g_gcnt[x];
    sg[x] = vg;
    __syncthreads();
    for (int off = 1; off < 512; off <<= 1) {
        int t = (x >= off) ? sg[x - off] : 0;
        __syncthreads();
        sg[x] += t;
        __syncthreads();
    }
    g_goff[x] = sg[x] - vg;
    if (x == 511) g_goff[NG] = sg[511];
}

__global__ void k_scan3() {
    int i = blockIdx.x * blockDim.x + threadIdx.x;
    if (i < NN) {
        int r = g_rowptr[i] + g_bsums[i >> 9];
        g_rowptr[i] = r;
        g_cursor[i] = r;
        g_inv[i] = rsqrtf((float)g_indeg[i] + 1.0f);   // deg = indeg + self loop
    }
    if (i == 0) g_rowptr[NN] = NE;
}

__global__ void k_scatter(const int* __restrict__ src, const int* __restrict__ dst) {
    for (int e = blockIdx.x * blockDim.x + threadIdx.x; e < NE; e += gridDim.x * blockDim.x) {
        int p = atomicAdd(&g_cursor[dst[e]], 1);
        g_colidx[p] = src[e];
    }
}

// ---------------- GEMM: g_hs = bf16( (X @ W) * inv[row] ) ----------------
// Block tile 128 x 160, 256 threads, per-thread 8 rows x 5 col-pairs, f32x2 FMA.
template <bool A_BF16>
__global__ __launch_bounds__(256) void k_gemm(const float* __restrict__ Xf,
                                              const unsigned short* __restrict__ Xh,
                                              const float* __restrict__ W,
                                              int M, int K) {
    __shared__ __align__(16) float As[32][128];   // k-major: [k][row]
    __shared__ __align__(16) float Bs[32][160];   // [k][col]
    const int tid = threadIdx.x;
    const int tx = tid & 15;
    const int ty = tid >> 4;
    const int rowBase = blockIdx.x * 128;

    unsigned long long acc[8][5];
#pragma unroll
    for (int q = 0; q < 8; q++)
#pragma unroll
        for (int p = 0; p < 5; p++) acc[q][p] = 0ull;

    for (int k0 = 0; k0 < K; k0 += 32) {
        if (A_BF16) {
#pragma unroll
            for (int i = 0; i < 2; i++) {
                int idx = tid + i * 256;          // < 512
                int row = idx & 127;
                int k8 = (idx >> 7) << 3;         // 0,8,16,24
                int gr = rowBase + row;
                uint4 v = make_uint4(0u, 0u, 0u, 0u);
                if (gr < M)
                    v = *reinterpret_cast<const uint4*>(Xh + (size_t)gr * K + k0 + k8);
                unsigned w[4] = {v.x, v.y, v.z, v.w};
#pragma unroll
                for (int j = 0; j < 4; j++) {
                    As[k8 + 2 * j][row] = bflo(w[j]);
                    As[k8 + 2 * j + 1][row] = bfhi(w[j]);
                }
            }
        } else {
#pragma unroll
            for (int i = 0; i < 4; i++) {
                int idx = tid + i * 256;          // < 1024
                int row = idx & 127;
                int k = (idx >> 7) << 2;          // 0,4,...,28
                int gr = rowBase + row;
                float4 v = make_float4(0.f, 0.f, 0.f, 0.f);
                if (gr < M) v = *reinterpret_cast<const float4*>(Xf + (size_t)gr * K + k0 + k);
                As[k + 0][row] = v.x;
                As[k + 1][row] = v.y;
                As[k + 2][row] = v.z;
                As[k + 3][row] = v.w;
            }
        }
#pragma unroll
        for (int i = 0; i < 5; i++) {
            int idx = tid + i * 256;          // < 1280
            int k = idx / 40;
            int c4 = idx % 40;
            *reinterpret_cast<float4*>(&Bs[k][c4 * 4]) =
                *reinterpret_cast<const float4*>(W + (size_t)(k0 + k) * HID + c4 * 4);
        }
        __syncthreads();
#pragma unroll
        for (int kk = 0; kk < 32; kk++) {
            float4 a0 = *reinterpret_cast<const float4*>(&As[kk][ty * 8]);
            float4 a1 = *reinterpret_cast<const float4*>(&As[kk][ty * 8 + 4]);
            unsigned long long pa[8];
            pa[0] = f2_dup(a0.x); pa[1] = f2_dup(a0.y);
            pa[2] = f2_dup(a0.z); pa[3] = f2_dup(a0.w);
            pa[4] = f2_dup(a1.x); pa[5] = f2_dup(a1.y);
            pa[6] = f2_dup(a1.z); pa[7] = f2_dup(a1.w);
            unsigned long long b[5];
#pragma unroll
            for (int p = 0; p < 5; p++) b[p] = ld2(&Bs[kk][32 * p + 2 * tx]);
#pragma unroll
            for (int q = 0; q < 8; q++)
#pragma unroll
                for (int p = 0; p < 5; p++) acc[q][p] = f2_fma(pa[q], b[p], acc[q][p]);
        }
        __syncthreads();
    }
    // epilogue: scale by inv[row], pack to bf16, store
#pragma unroll
    for (int q = 0; q < 8; q++) {
        int gr = rowBase + ty * 8 + q;
        if (gr < M) {
            float s = g_inv[gr];
            unsigned short* dstp = g_hs + (size_t)gr * HID;
#pragma unroll
            for (int p = 0; p < 5; p++) {
                F2U t; t.u = acc[q][p];
                *reinterpret_cast<unsigned*>(dstp + 32 * p + 2 * tx) =
                    bfpack(t.f2.x * s, t.f2.y * s);
            }
        }
    }
}

// ---------------- Aggregate + bias + BN + ReLU (bf16 rows, fp32 accum) ----------------
// Lane owns elements [4*lane..4*lane+3] (uint2), lanes 0..15 own [128+2*lane,+1] (uint).
__global__ __launch_bounds__(256) void k_agg(const float* __restrict__ bias,
                                             const float* __restrict__ gam,
                                             const float* __restrict__ bet,
                                             const float* __restrict__ mean,
                                             const float* __restrict__ var) {
    int d = (blockIdx.x * blockDim.x + threadIdx.x) >> 5;
    int lane = threadIdx.x & 31;
    if (d >= NN) return;
    bool tail = lane < 16;

    const unsigned short* hr = g_hs + (size_t)d * HID;

    float a0, a1, a2, a3, t0 = 0.f, t1 = 0.f;
    {
        uint2 v = *reinterpret_cast<const uint2*>(hr + 4 * lane);
        a0 = bflo(v.x); a1 = bfhi(v.x); a2 = bflo(v.y); a3 = bfhi(v.y);
        if (tail) {
            unsigned u = *reinterpret_cast<const unsigned*>(hr + 128 + 2 * lane);
            t0 = bflo(u); t1 = bfhi(u);
        }
    }

    // hoisted BN constants
    int c = 4 * lane;
    int ct = 128 + 2 * lane;
    float idv = g_inv[d];
    float A0 = gam[c]     * rsqrtf(var[c]     + BN_EPS);
    float A1 = gam[c + 1] * rsqrtf(var[c + 1] + BN_EPS);
    float A2 = gam[c + 2] * rsqrtf(var[c + 2] + BN_EPS);
    float A3 = gam[c + 3] * rsqrtf(var[c + 3] + BN_EPS);
    float Q0 = (bias[c]     - mean[c])     * A0 + bet[c];
    float Q1 = (bias[c + 1] - mean[c + 1]) * A1 + bet[c + 1];
    float Q2 = (bias[c + 2] - mean[c + 2]) * A2 + bet[c + 2];
    float Q3 = (bias[c + 3] - mean[c + 3]) * A3 + bet[c + 3];
    float A4 = 0.f, A5 = 0.f, Q4 = 0.f, Q5 = 0.f;
    if (tail) {
        A4 = gam[ct]     * rsqrtf(var[ct]     + BN_EPS);
        A5 = gam[ct + 1] * rsqrtf(var[ct + 1] + BN_EPS);
        Q4 = (bias[ct]     - mean[ct])     * A4 + bet[ct];
        Q5 = (bias[ct + 1] - mean[ct + 1]) * A5 + bet[ct + 1];
    }

    int beg = g_rowptr[d], end = g_rowptr[d + 1];
    for (int e0 = beg; e0 < end; e0 += 32) {
        int n = min(32, end - e0);
        int myidx = (lane < n) ? g_colidx[e0 + lane] : 0;
        for (int t = 0; t < n; t++) {
            int s = __shfl_sync(0xffffffffu, myidx, t);
            const unsigned short* r = g_hs + (size_t)s * HID;
            uint2 v = *reinterpret_cast<const uint2*>(r + 4 * lane);
            a0 += bflo(v.x); a1 += bfhi(v.x);
            a2 += bflo(v.y); a3 += bfhi(v.y);
            if (tail) {
                unsigned u = *reinterpret_cast<const unsigned*>(r + 128 + 2 * lane);
                t0 += bflo(u); t1 += bfhi(u);
            }
        }
    }

    unsigned short* o = g_feat + (size_t)d * HID;
    float y0 = fmaxf(fmaf(a0, idv * A0, Q0), 0.f);
    float y1 = fmaxf(fmaf(a1, idv * A1, Q1), 0.f);
    float y2 = fmaxf(fmaf(a2, idv * A2, Q2), 0.f);
    float y3 = fmaxf(fmaf(a3, idv * A3, Q3), 0.f);
    uint2 ov;
    ov.x = bfpack(y0, y1);
    ov.y = bfpack(y2, y3);
    *reinterpret_cast<uint2*>(o + 4 * lane) = ov;
    if (tail) {
        float y4 = fmaxf(fmaf(t0, idv * A4, Q4), 0.f);
        float y5 = fmaxf(fmaf(t1, idv * A5, Q5), 0.f);
        *reinterpret_cast<unsigned*>(o + 128 + 2 * lane) = bfpack(y4, y5);
    }
}

// ---------------- mean pool per graph ----------------
__global__ void k_pool() {   // grid: NG blocks x 80 threads (2 cols/thread)
    int g = blockIdx.x;
    int j = threadIdx.x;
    int s0 = g_goff[g];
    int cnt = g_goff[g + 1] - s0;
    float sx = 0.f, sy = 0.f;
    for (int i = 0; i < cnt; i++) {
        unsigned u = *reinterpret_cast<const unsigned*>(g_feat + (size_t)(s0 + i) * HID + 2 * j);
        sx += bflo(u); sy += bfhi(u);
    }
    float invc = 1.f / fmaxf((float)cnt, 1.f);
    g_pooled[g * HID + 2 * j] = sx * invc;
    g_pooled[g * HID + 2 * j + 1] = sy * invc;
}

// ---------------- MLP head ----------------
__global__ void k_head(const float* __restrict__ Wc1, const float* __restrict__ bc1,
                       const float* __restrict__ Wc2, const float* __restrict__ bc2,
                       float* __restrict__ out) {   // grid: NG blocks x 80 threads
    __shared__ float p[HID];
    __shared__ float z[80];
    int g = blockIdx.x;
    int j = threadIdx.x;
    p[j] = g_pooled[g * HID + j];
    p[j + 80] = g_pooled[g * HID + j + 80];
    __syncthreads();
    float s = bc1[j];
    for (int i = 0; i < HID; i++) s = fmaf(p[i], Wc1[i * 80 + j], s);
    z[j] = fmaxf(s, 0.f);
    __syncthreads();
    if (j < NC) {
        float o = bc2[j];
        for (int i = 0; i < 80; i++) o = fmaf(z[i], Wc2[i * NC + j], o);
        out[g * NC + j] = o;
    }
}

// ---------------- launch ----------------
extern "C" void kernel_launch(void* const* d_in, const int* in_sizes, int n_in,
                              void* d_out, int out_size) {
    const float* x   = (const float*)d_in[0];
    const int* ei    = (const int*)d_in[1];
    const int* batch = (const int*)d_in[2];
    const float* W1  = (const float*)d_in[3];
    const float* b1  = (const float*)d_in[4];
    const float* W2  = (const float*)d_in[5];
    const float* b2  = (const float*)d_in[6];
    const float* W3  = (const float*)d_in[7];
    const float* b3  = (const float*)d_in[8];
    const float* g1  = (const float*)d_in[9];
    const float* be1 = (const float*)d_in[10];
    const float* m1  = (const float*)d_in[11];
    const float* v1  = (const float*)d_in[12];
    const float* g2  = (const float*)d_in[13];
    const float* be2 = (const float*)d_in[14];
    const float* m2  = (const float*)d_in[15];
    const float* v2  = (const float*)d_in[16];
    const float* g3  = (const float*)d_in[17];
    const float* be3 = (const float*)d_in[18];
    const float* m3  = (const float*)d_in[19];
    const float* v3  = (const float*)d_in[20];
    const float* Wc1 = (const float*)d_in[21];
    const float* bc1 = (const float*)d_in[22];
    const float* Wc2 = (const float*)d_in[23];
    const float* bc2 = (const float*)d_in[24];
    const int* src = ei;
    const int* dst = ei + NE;
    float* out = (float*)d_out;

    unsigned short* feat_ptr = nullptr;
    cudaGetSymbolAddress((void**)&feat_ptr, g_feat);
    void* indeg_ptr = nullptr;
    cudaGetSymbolAddress(&indeg_ptr, g_indeg);
    void* gcnt_ptr = nullptr;
    cudaGetSymbolAddress(&gcnt_ptr, g_gcnt);

    // ---- graph structure (rebuilt each call; deterministic work) ----
    cudaMemsetAsync(indeg_ptr, 0, NN * sizeof(int));
    cudaMemsetAsync(gcnt_ptr, 0, NG * sizeof(int));
    k_count2<<<2048, 256>>>(dst, batch);
    k_scan1<<<(NN + 511) / 512, 512>>>();
    k_scan2g<<<1, 512>>>((NN + 511) / 512);
    k_scan3<<<(NN + 255) / 256, 256>>>();
    k_scatter<<<2048, 256>>>(src, dst);

    const int gemm_blocks = (NN + 127) / 128;
    const int agg_blocks = (NN + 7) / 8;   // 8 warps per 256-thread block

    // layer 1 (fp32 A)
    k_gemm<false><<<gemm_blocks, 256>>>(x, nullptr, W1, NN, FIN);
    k_agg<<<agg_blocks, 256>>>(b1, g1, be1, m1, v1);
    // layer 2 (bf16 A)
    k_gemm<true><<<gemm_blocks, 256>>>(nullptr, feat_ptr, W2, NN, HID);
    k_agg<<<agg_blocks, 256>>>(b2, g2, be2, m2, v2);
    // layer 3 (bf16 A)
    k_gemm<true><<<gemm_blocks, 256>>>(nullptr, feat_ptr, W3, NN, HID);
    k_agg<<<agg_blocks, 256>>>(b3, g3, be3, m3, v3);

    // pool + head
    k_pool<<<NG, 80>>>();
    k_head<<<NG, 80>>>(Wc1, bc1, Wc2, bc2, out);
}

// round 7
// speedup vs baseline: 1.9359x; 1.1123x over previous
#include <cuda_runtime.h>
#include <math.h>

#define NN 50000
#define NE 1600000
#define FIN 128
#define HID 160
#define NG 512
#define NC 2
#define BN_EPS 1e-5f

// ---------------- scratch (static __device__, no allocs) ----------------
__device__ __align__(16) unsigned short g_hs[NN * HID];    // bf16 scaled linear output
__device__ __align__(16) unsigned short g_feat[NN * HID];  // bf16 layer output features
__device__ float g_inv[NN];                                // 1/sqrt(deg)
__device__ int   g_indeg[NN];
__device__ int   g_rowptr[NN + 1];
__device__ int   g_cursor[NN];
__device__ int   g_colidx[NE];
__device__ int   g_bsums[128];
__device__ int   g_gcnt[NG];
__device__ int   g_goff[NG + 1];
__device__ float g_pooled[NG * HID];

// ---------------- bf16 helpers (ALU-only unpack) ----------------
__device__ __forceinline__ float bflo(unsigned u) { return __uint_as_float(u << 16); }
__device__ __forceinline__ float bfhi(unsigned u) { return __uint_as_float(u & 0xffff0000u); }
__device__ __forceinline__ unsigned bfpack(float lo, float hi) {
    unsigned r;
    asm("cvt.rn.bf16x2.f32 %0, %1, %2;" : "=r"(r) : "f"(hi), "f"(lo));
    return r;
}

// mma.m16n8k16 row.col bf16 -> f32 accumulate
__device__ __forceinline__ void mma_bf16(float* d, const unsigned* a, unsigned b0, unsigned b1) {
    asm("mma.sync.aligned.m16n8k16.row.col.f32.bf16.bf16.f32 "
        "{%0,%1,%2,%3}, {%4,%5,%6,%7}, {%8,%9}, {%0,%1,%2,%3};"
        : "+f"(d[0]), "+f"(d[1]), "+f"(d[2]), "+f"(d[3])
        : "r"(a[0]), "r"(a[1]), "r"(a[2]), "r"(a[3]), "r"(b0), "r"(b1));
}

// ---------------- build kernels ----------------
__global__ void k_zero() {
    int i = blockIdx.x * blockDim.x + threadIdx.x;
    if (i < NN) g_indeg[i] = 0;
    if (i < NG) g_gcnt[i] = 0;
}

__global__ void k_count2(const int* __restrict__ dst, const int* __restrict__ batch) {
    int stride = gridDim.x * blockDim.x;
    int t0 = blockIdx.x * blockDim.x + threadIdx.x;
    for (int e = t0; e < NE; e += stride)
        atomicAdd(&g_indeg[dst[e]], 1);
    for (int i = t0; i < NN; i += stride)
        atomicAdd(&g_gcnt[batch[i]], 1);
}

__global__ void k_scan1() {   // grid: 98 blocks x 512
    __shared__ int sh[512];
    int i = blockIdx.x * 512 + threadIdx.x;
    int v = (i < NN) ? g_indeg[i] : 0;
    sh[threadIdx.x] = v;
    __syncthreads();
    for (int off = 1; off < 512; off <<= 1) {
        int t = (threadIdx.x >= off) ? sh[threadIdx.x - off] : 0;
        __syncthreads();
        sh[threadIdx.x] += t;
        __syncthreads();
    }
    if (i < NN) g_rowptr[i] = sh[threadIdx.x] - v;
    if (threadIdx.x == 511) g_bsums[blockIdx.x] = sh[511];
}

__global__ void k_scan2g(int nb) {   // 1 block x 512
    __shared__ int sb[128];
    __shared__ int sg[512];
    int x = threadIdx.x;
    int vb = 0;
    if (x < 128) { vb = (x < nb) ? g_bsums[x] : 0; sb[x] = vb; }
    __syncthreads();
    for (int off = 1; off < 128; off <<= 1) {
        int t = (x < 128 && x >= off) ? sb[x - off] : 0;
        __syncthreads();
        if (x < 128) sb[x] += t;
        __syncthreads();
    }
    if (x < nb) g_bsums[x] = sb[x] - vb;   // exclusive
    int vg = g_gcnt[x];
    sg[x] = vg;
    __syncthreads();
    for (int off = 1; off < 512; off <<= 1) {
        int t = (x >= off) ? sg[x - off] : 0;
        __syncthreads();
        sg[x] += t;
        __syncthreads();
    }
    g_goff[x] = sg[x] - vg;
    if (x == 511) g_goff[NG] = sg[511];
}

__global__ void k_scan3() {
    int i = blockIdx.x * blockDim.x + threadIdx.x;
    if (i < NN) {
        int r = g_rowptr[i] + g_bsums[i >> 9];
        g_rowptr[i] = r;
        g_cursor[i] = r;
        g_inv[i] = rsqrtf((float)g_indeg[i] + 1.0f);
    }
    if (i == 0) g_rowptr[NN] = NE;
}

__global__ void k_scatter(const int* __restrict__ src, const int* __restrict__ dst) {
    for (int e = blockIdx.x * blockDim.x + threadIdx.x; e < NE; e += gridDim.x * blockDim.x) {
        int p = atomicAdd(&g_cursor[dst[e]], 1);
        g_colidx[p] = src[e];
    }
}

// ---------------- tensor-core GEMM: g_hs = bf16( (X @ W) * inv[row] ) ----------------
// Block: 128 rows x 160 cols, 256 threads = 8 warps (4 m-warps x 2 n-warps).
// W split into bf16 hi + bf16 lo, two MMA passes, fp32 accum.
// As2: [k2(16)][row(128)] packed bf16x2 (k-pairs), row stride 137.
// Bs2: [k2(16)][j(8)][slot(48)] packed bf16x2, hi slots wn*12+tt, lo +24.
template <bool A_BF16>
__global__ __launch_bounds__(256) void k_gemm_tc(const float* __restrict__ Xf,
                                                 const unsigned short* __restrict__ Xh,
                                                 const float* __restrict__ W,
                                                 int M, int K) {
    __shared__ unsigned As2[16 * 137];
    __shared__ unsigned Bs2[16 * 392];
    const int tid = threadIdx.x;
    const int wid = tid >> 5;
    const int lane = tid & 31;
    const int wm = (wid & 3) * 32;
    const int wn = wid >> 2;           // 0 or 1
    const int r = lane >> 2;
    const int c = lane & 3;
    const int rowBase = blockIdx.x * 128;

    float acc[2][10][4];
#pragma unroll
    for (int mt = 0; mt < 2; mt++)
#pragma unroll
        for (int nt = 0; nt < 10; nt++)
#pragma unroll
            for (int i = 0; i < 4; i++) acc[mt][nt][i] = 0.f;

    for (int k0 = 0; k0 < K; k0 += 32) {
        // ---- A tile fill ----
        if (A_BF16) {
            const unsigned* Xrow = reinterpret_cast<const unsigned*>(Xh);
#pragma unroll
            for (int i = 0; i < 8; i++) {
                int idx = tid + i * 256;        // 0..2047
                int u = idx & 15;               // local k2
                int row = idx >> 4;             // 0..127
                int gr = rowBase + row;
                unsigned v = 0u;
                if (gr < M) v = Xrow[(size_t)gr * (HID / 2) + (k0 >> 1) + u];
                As2[u * 137 + row] = v;
            }
        } else {
#pragma unroll
            for (int i = 0; i < 8; i++) {
                int idx = tid + i * 256;
                int u = idx & 15;
                int row = idx >> 4;
                int gr = rowBase + row;
                float2 v = make_float2(0.f, 0.f);
                if (gr < M) v = *reinterpret_cast<const float2*>(Xf + (size_t)gr * K + k0 + 2 * u);
                As2[u * 137 + row] = bfpack(v.x, v.y);
            }
        }
        // ---- B tile fill (hi/lo split) ----
#pragma unroll
        for (int i = 0; i < 10; i++) {
            int idx = tid + i * 256;            // 0..2559
            int cc = idx % 160;
            int k2 = idx / 160;                 // 0..15
            float w0 = W[(size_t)(k0 + 2 * k2) * HID + cc];
            float w1 = W[(size_t)(k0 + 2 * k2 + 1) * HID + cc];
            unsigned hp = bfpack(w0, w1);       // rounded bf16 pair
            float h0 = bflo(hp), h1 = bfhi(hp);
            unsigned lp = bfpack(w0 - h0, w1 - h1);
            int j = cc & 7;
            int tile = cc >> 3;                 // 0..19
            int slot = (tile >= 10) ? (12 + tile - 10) : tile;
            unsigned* base = &Bs2[k2 * 392 + j * 48];
            base[slot] = hp;
            base[24 + slot] = lp;
        }
        __syncthreads();

        // ---- compute: 2 k-steps of 16 ----
#pragma unroll
        for (int ks = 0; ks < 2; ks++) {
            int kb = ks * 8;
            unsigned a[2][4];
#pragma unroll
            for (int mt = 0; mt < 2; mt++) {
                int rb = wm + mt * 16 + r;
                a[mt][0] = As2[(kb + c) * 137 + rb];
                a[mt][1] = As2[(kb + c) * 137 + rb + 8];
                a[mt][2] = As2[(kb + c + 4) * 137 + rb];
                a[mt][3] = As2[(kb + c + 4) * 137 + rb + 8];
            }
            const unsigned* b0base = &Bs2[(kb + c) * 392 + r * 48 + wn * 12];
            const unsigned* b1base = &Bs2[(kb + c + 4) * 392 + r * 48 + wn * 12];
#pragma unroll
            for (int pass = 0; pass < 2; pass++) {
                int off = pass * 24;
                uint4 p0 = *reinterpret_cast<const uint4*>(b0base + off);
                uint4 q0 = *reinterpret_cast<const uint4*>(b1base + off);
                mma_bf16(acc[0][0], a[0], p0.x, q0.x);
                mma_bf16(acc[1][0], a[1], p0.x, q0.x);
                mma_bf16(acc[0][1], a[0], p0.y, q0.y);
                mma_bf16(acc[1][1], a[1], p0.y, q0.y);
                mma_bf16(acc[0][2], a[0], p0.z, q0.z);
                mma_bf16(acc[1][2], a[1], p0.z, q0.z);
                mma_bf16(acc[0][3], a[0], p0.w, q0.w);
                mma_bf16(acc[1][3], a[1], p0.w, q0.w);
                uint4 p1 = *reinterpret_cast<const uint4*>(b0base + off + 4);
                uint4 q1 = *reinterpret_cast<const uint4*>(b1base + off + 4);
                mma_bf16(acc[0][4], a[0], p1.x, q1.x);
                mma_bf16(acc[1][4], a[1], p1.x, q1.x);
                mma_bf16(acc[0][5], a[0], p1.y, q1.y);
                mma_bf16(acc[1][5], a[1], p1.y, q1.y);
                mma_bf16(acc[0][6], a[0], p1.z, q1.z);
                mma_bf16(acc[1][6], a[1], p1.z, q1.z);
                mma_bf16(acc[0][7], a[0], p1.w, q1.w);
                mma_bf16(acc[1][7], a[1], p1.w, q1.w);
                uint2 p2 = *reinterpret_cast<const uint2*>(b0base + off + 8);
                uint2 q2 = *reinterpret_cast<const uint2*>(b1base + off + 8);
                mma_bf16(acc[0][8], a[0], p2.x, q2.x);
                mma_bf16(acc[1][8], a[1], p2.x, q2.x);
                mma_bf16(acc[0][9], a[0], p2.y, q2.y);
                mma_bf16(acc[1][9], a[1], p2.y, q2.y);
            }
        }
        __syncthreads();
    }

    // ---- epilogue: scale by inv[row], pack bf16, store ----
#pragma unroll
    for (int mt = 0; mt < 2; mt++) {
        int row0 = rowBase + wm + mt * 16 + r;
        int row1 = row0 + 8;
        float s0 = (row0 < M) ? g_inv[row0] : 0.f;
        float s1 = (row1 < M) ? g_inv[row1] : 0.f;
#pragma unroll
        for (int nt = 0; nt < 10; nt++) {
            int col = wn * 80 + nt * 8 + 2 * c;
            if (row0 < M)
                *reinterpret_cast<unsigned*>(g_hs + (size_t)row0 * HID + col) =
                    bfpack(acc[mt][nt][0] * s0, acc[mt][nt][1] * s0);
            if (row1 < M)
                *reinterpret_cast<unsigned*>(g_hs + (size_t)row1 * HID + col) =
                    bfpack(acc[mt][nt][2] * s1, acc[mt][nt][3] * s1);
        }
    }
}

// ---------------- Aggregate + bias + BN + ReLU (bf16 rows, fp32 accum) ----------------
__global__ __launch_bounds__(256) void k_agg(const float* __restrict__ bias,
                                             const float* __restrict__ gam,
                                             const float* __restrict__ bet,
                                             const float* __restrict__ mean,
                                             const float* __restrict__ var) {
    int d = (blockIdx.x * blockDim.x + threadIdx.x) >> 5;
    int lane = threadIdx.x & 31;
    if (d >= NN) return;
    bool tail = lane < 16;

    const unsigned short* hr = g_hs + (size_t)d * HID;

    float a0, a1, a2, a3, t0 = 0.f, t1 = 0.f;
    {
        uint2 v = *reinterpret_cast<const uint2*>(hr + 4 * lane);
        a0 = bflo(v.x); a1 = bfhi(v.x); a2 = bflo(v.y); a3 = bfhi(v.y);
        if (tail) {
            unsigned u = *reinterpret_cast<const unsigned*>(hr + 128 + 2 * lane);
            t0 = bflo(u); t1 = bfhi(u);
        }
    }

    int c = 4 * lane;
    int ct = 128 + 2 * lane;
    float idv = g_inv[d];
    float A0 = gam[c]     * rsqrtf(var[c]     + BN_EPS);
    float A1 = gam[c + 1] * rsqrtf(var[c + 1] + BN_EPS);
    float A2 = gam[c + 2] * rsqrtf(var[c + 2] + BN_EPS);
    float A3 = gam[c + 3] * rsqrtf(var[c + 3] + BN_EPS);
    float Q0 = (bias[c]     - mean[c])     * A0 + bet[c];
    float Q1 = (bias[c + 1] - mean[c + 1]) * A1 + bet[c + 1];
    float Q2 = (bias[c + 2] - mean[c + 2]) * A2 + bet[c + 2];
    float Q3 = (bias[c + 3] - mean[c + 3]) * A3 + bet[c + 3];
    float A4 = 0.f, A5 = 0.f, Q4 = 0.f, Q5 = 0.f;
    if (tail) {
        A4 = gam[ct]     * rsqrtf(var[ct]     + BN_EPS);
        A5 = gam[ct + 1] * rsqrtf(var[ct + 1] + BN_EPS);
        Q4 = (bias[ct]     - mean[ct])     * A4 + bet[ct];
        Q5 = (bias[ct + 1] - mean[ct + 1]) * A5 + bet[ct + 1];
    }

    int beg = g_rowptr[d], end = g_rowptr[d + 1];
    for (int e0 = beg; e0 < end; e0 += 32) {
        int n = min(32, end - e0);
        int myidx = (lane < n) ? g_colidx[e0 + lane] : 0;
        for (int t = 0; t < n; t++) {
            int s = __shfl_sync(0xffffffffu, myidx, t);
            const unsigned short* rr = g_hs + (size_t)s * HID;
            uint2 v = *reinterpret_cast<const uint2*>(rr + 4 * lane);
            a0 += bflo(v.x); a1 += bfhi(v.x);
            a2 += bflo(v.y); a3 += bfhi(v.y);
            if (tail) {
                unsigned u = *reinterpret_cast<const unsigned*>(rr + 128 + 2 * lane);
                t0 += bflo(u); t1 += bfhi(u);
            }
        }
    }

    unsigned short* o = g_feat + (size_t)d * HID;
    float y0 = fmaxf(fmaf(a0, idv * A0, Q0), 0.f);
    float y1 = fmaxf(fmaf(a1, idv * A1, Q1), 0.f);
    float y2 = fmaxf(fmaf(a2, idv * A2, Q2), 0.f);
    float y3 = fmaxf(fmaf(a3, idv * A3, Q3), 0.f);
    uint2 ov;
    ov.x = bfpack(y0, y1);
    ov.y = bfpack(y2, y3);
    *reinterpret_cast<uint2*>(o + 4 * lane) = ov;
    if (tail) {
        float y4 = fmaxf(fmaf(t0, idv * A4, Q4), 0.f);
        float y5 = fmaxf(fmaf(t1, idv * A5, Q5), 0.f);
        *reinterpret_cast<unsigned*>(o + 128 + 2 * lane) = bfpack(y4, y5);
    }
}

// ---------------- mean pool per graph ----------------
__global__ void k_pool() {   // grid: NG blocks x 80 threads (2 cols/thread)
    int g = blockIdx.x;
    int j = threadIdx.x;
    int s0 = g_goff[g];
    int cnt = g_goff[g + 1] - s0;
    float sx = 0.f, sy = 0.f;
    for (int i = 0; i < cnt; i++) {
        unsigned u = *reinterpret_cast<const unsigned*>(g_feat + (size_t)(s0 + i) * HID + 2 * j);
        sx += bflo(u); sy += bfhi(u);
    }
    float invc = 1.f / fmaxf((float)cnt, 1.f);
    g_pooled[g * HID + 2 * j] = sx * invc;
    g_pooled[g * HID + 2 * j + 1] = sy * invc;
}

// ---------------- MLP head ----------------
__global__ void k_head(const float* __restrict__ Wc1, const float* __restrict__ bc1,
                       const float* __restrict__ Wc2, const float* __restrict__ bc2,
                       float* __restrict__ out) {   // grid: NG blocks x 80 threads
    __shared__ float p[HID];
    __shared__ float z[80];
    int g = blockIdx.x;
    int j = threadIdx.x;
    p[j] = g_pooled[g * HID + j];
    p[j + 80] = g_pooled[g * HID + j + 80];
    __syncthreads();
    float s = bc1[j];
    for (int i = 0; i < HID; i++) s = fmaf(p[i], Wc1[i * 80 + j], s);
    z[j] = fmaxf(s, 0.f);
    __syncthreads();
    if (j < NC) {
        float o = bc2[j];
        for (int i = 0; i < 80; i++) o = fmaf(z[i], Wc2[i * NC + j], o);
        out[g * NC + j] = o;
    }
}

// ---------------- launch ----------------
extern "C" void kernel_launch(void* const* d_in, const int* in_sizes, int n_in,
                              void* d_out, int out_size) {
    const float* x   = (const float*)d_in[0];
    const int* ei    = (const int*)d_in[1];
    const int* batch = (const int*)d_in[2];
    const float* W1  = (const float*)d_in[3];
    const float* b1  = (const float*)d_in[4];
    const float* W2  = (const float*)d_in[5];
    const float* b2  = (const float*)d_in[6];
    const float* W3  = (const float*)d_in[7];
    const float* b3  = (const float*)d_in[8];
    const float* g1  = (const float*)d_in[9];
    const float* be1 = (const float*)d_in[10];
    const float* m1  = (const float*)d_in[11];
    const float* v1  = (const float*)d_in[12];
    const float* g2  = (const float*)d_in[13];
    const float* be2 = (const float*)d_in[14];
    const float* m2  = (const float*)d_in[15];
    const float* v2  = (const float*)d_in[16];
    const float* g3  = (const float*)d_in[17];
    const float* be3 = (const float*)d_in[18];
    const float* m3  = (const float*)d_in[19];
    const float* v3  = (const float*)d_in[20];
    const float* Wc1 = (const float*)d_in[21];
    const float* bc1 = (const float*)d_in[22];
    const float* Wc2 = (const float*)d_in[23];
    const float* bc2 = (const float*)d_in[24];
    const int* src = ei;
    const int* dst = ei + NE;
    float* out = (float*)d_out;

    unsigned short* feat_ptr = nullptr;
    cudaGetSymbolAddress((void**)&feat_ptr, g_feat);

    const int gemm_blocks = (NN + 127) / 128;
    const int agg_blocks = (NN + 7) / 8;

    // ---- graph structure + layer 1 GEMM early (gemm only needs g_inv) ----
    k_zero<<<(NN + 255) / 256, 256>>>();
    k_count2<<<2048, 256>>>(dst, batch);
    k_scan1<<<(NN + 511) / 512, 512>>>();
    k_scan2g<<<1, 512>>>((NN + 511) / 512);
    k_scan3<<<(NN + 255) / 256, 256>>>();
    k_gemm_tc<false><<<gemm_blocks, 256>>>(x, nullptr, W1, NN, FIN);   // ncu capture slot
    k_scatter<<<2048, 256>>>(src, dst);

    // layer 1 aggregate
    k_agg<<<agg_blocks, 256>>>(b1, g1, be1, m1, v1);
    // layer 2
    k_gemm_tc<true><<<gemm_blocks, 256>>>(nullptr, feat_ptr, W2, NN, HID);
    k_agg<<<agg_blocks, 256>>>(b2, g2, be2, m2, v2);
    // layer 3
    k_gemm_tc<true><<<gemm_blocks, 256>>>(nullptr, feat_ptr, W3, NN, HID);
    k_agg<<<agg_blocks, 256>>>(b3, g3, be3, m3, v3);

    // pool + head
    k_pool<<<NG, 80>>>();
    k_head<<<NG, 80>>>(Wc1, bc1, Wc2, bc2, out);
}

// round 8
// speedup vs baseline: 1.9783x; 1.0219x over previous
#include <cuda_runtime.h>
#include <math.h>

#define NN 50000
#define NE 1600000
#define FIN 128
#define HID 160
#define NG 512
#define NC 2
#define BN_EPS 1e-5f
#define TILES 98          // ceil(NN/512)

// ---------------- scratch (static __device__, no allocs) ----------------
__device__ __align__(16) unsigned short g_hs[NN * HID];    // bf16 scaled linear output
__device__ __align__(16) unsigned short g_feat[NN * HID];  // bf16 layer output features
__device__ float g_inv[NN];                                // 1/sqrt(deg)
__device__ int   g_indeg[NN];
__device__ int   g_rowptr[NN + 1];
__device__ int   g_cursor[NN];
__device__ int   g_colidx[NE];
__device__ int   g_tileagg[TILES];
__device__ int   g_tileflag[TILES];
__device__ int   g_gcnt[NG];
__device__ int   g_goff[NG + 1];
__device__ float g_pooled[NG * HID];
// packed hi/lo bf16x2 weight tiles, smem-tile layout: [ktile][k2(16)][j(8)][slot(48)] (+8 pad/k2)
// L1: 4 ktiles @0, L2: 5 @25088, L3: 5 @56448
__device__ __align__(16) unsigned g_wbuf[87808];

// ---------------- bf16 helpers (ALU-only unpack) ----------------
__device__ __forceinline__ float bflo(unsigned u) { return __uint_as_float(u << 16); }
__device__ __forceinline__ float bfhi(unsigned u) { return __uint_as_float(u & 0xffff0000u); }
__device__ __forceinline__ unsigned bfpack(float lo, float hi) {
    unsigned r;
    asm("cvt.rn.bf16x2.f32 %0, %1, %2;" : "=r"(r) : "f"(hi), "f"(lo));
    return r;
}

__device__ __forceinline__ void mma_bf16(float* d, const unsigned* a, unsigned b0, unsigned b1) {
    asm("mma.sync.aligned.m16n8k16.row.col.f32.bf16.bf16.f32 "
        "{%0,%1,%2,%3}, {%4,%5,%6,%7}, {%8,%9}, {%0,%1,%2,%3};"
        : "+f"(d[0]), "+f"(d[1]), "+f"(d[2]), "+f"(d[3])
        : "r"(a[0]), "r"(a[1]), "r"(a[2]), "r"(a[3]), "r"(b0), "r"(b1));
}

// ---------------- weight prep: pack hi/lo bf16x2 tiles ----------------
// one thread per (layer, ktile, k2, cc): L1 10240, L2 12800, L3 12800 -> 35840 total
__global__ void k_wprep(const float* __restrict__ W1, const float* __restrict__ W2,
                        const float* __restrict__ W3) {
    int idx = blockIdx.x * blockDim.x + threadIdx.x;
    if (idx >= 35840) return;
    const float* W;
    int base, rel;
    if (idx < 10240)      { W = W1; base = 0;     rel = idx; }
    else if (idx < 23040) { W = W2; base = 25088; rel = idx - 10240; }
    else                  { W = W3; base = 56448; rel = idx - 23040; }
    int cc = rel % 160;
    int t = rel / 160;
    int k2 = t & 15;
    int kt = t >> 4;
    int row = kt * 32 + 2 * k2;
    float w0 = W[(size_t)row * HID + cc];
    float w1 = W[(size_t)(row + 1) * HID + cc];
    unsigned hp = bfpack(w0, w1);
    float h0 = bflo(hp), h1 = bfhi(hp);
    unsigned lp = bfpack(w0 - h0, w1 - h1);
    int j = cc & 7;
    int tile = cc >> 3;
    int slot = (tile >= 10) ? (tile + 2) : tile;
    unsigned* dstp = g_wbuf + base + kt * 6272 + k2 * 392 + j * 48;
    dstp[slot] = hp;
    dstp[slot + 24] = lp;
}

// ---------------- build kernels ----------------
__global__ void k_zero() {
    int i = blockIdx.x * blockDim.x + threadIdx.x;
    if (i < NN) g_indeg[i] = 0;
    if (i < NG) g_gcnt[i] = 0;
    if (i < TILES) g_tileflag[i] = 0;
}

__global__ void k_count2(const int* __restrict__ dst, const int* __restrict__ batch) {
    int stride = gridDim.x * blockDim.x;
    int t0 = blockIdx.x * blockDim.x + threadIdx.x;
    for (int e = t0; e < NE; e += stride)
        atomicAdd(&g_indeg[dst[e]], 1);
    for (int i = t0; i < NN; i += stride)
        atomicAdd(&g_gcnt[batch[i]], 1);
}

// single-pass scan: 98 tiles, immediate aggregate publish + full lookback.
// also computes inv/cursor, and the graph-offset scan in the last tile.
__global__ void k_scanall() {
    __shared__ int sh[512];
    __shared__ int s_sum;
    int bid = blockIdx.x, tid = threadIdx.x;
    int i = bid * 512 + tid;
    int v = (i < NN) ? g_indeg[i] : 0;
    sh[tid] = v;
    __syncthreads();
    for (int off = 1; off < 512; off <<= 1) {
        int t = (tid >= off) ? sh[tid - off] : 0;
        __syncthreads();
        sh[tid] += t;
        __syncthreads();
    }
    if (tid == 0) s_sum = 0;
    if (tid == 511) {
        g_tileagg[bid] = sh[511];
        __threadfence();
        g_tileflag[bid] = 1;
    }
    __syncthreads();
    // lookback: sum all predecessor aggregates (published independently)
    volatile int* vflag = (volatile int*)g_tileflag;
    volatile int* vagg = (volatile int*)g_tileagg;
    int prev = 0;
    for (int t = tid; t < bid; t += 512) {
        while (vflag[t] == 0) {}
        prev += vagg[t];
    }
    if (prev) atomicAdd(&s_sum, prev);
    __syncthreads();
    int excl = sh[tid] - v + s_sum;
    if (i < NN) {
        g_rowptr[i] = excl;
        g_cursor[i] = excl;
        g_inv[i] = rsqrtf((float)v + 1.0f);
    }
    if (bid == 0 && tid == 0) g_rowptr[NN] = NE;
    // graph-offset scan (g_gcnt ready since k_count2 finished before this kernel)
    if (bid == TILES - 1) {
        __syncthreads();
        int vg = g_gcnt[tid];
        sh[tid] = vg;
        __syncthreads();
        for (int off = 1; off < 512; off <<= 1) {
            int t = (tid >= off) ? sh[tid - off] : 0;
            __syncthreads();
            sh[tid] += t;
            __syncthreads();
        }
        g_goff[tid] = sh[tid] - vg;
        if (tid == 511) g_goff[NG] = sh[511];
    }
}

__global__ void k_scatter(const int* __restrict__ src, const int* __restrict__ dst) {
    for (int e = blockIdx.x * blockDim.x + threadIdx.x; e < NE; e += gridDim.x * blockDim.x) {
        int p = atomicAdd(&g_cursor[dst[e]], 1);
        g_colidx[p] = src[e];
    }
}

// ---------------- tensor-core GEMM: g_hs = bf16( (X @ W) * inv[row] ) ----------------
// Block: 128 rows x 160 cols, 256 threads = 8 warps (4 m-warps x 2 n-warps).
// B tiles precomputed in g_wbuf (hi/lo split); two MMA passes, fp32 accum.
template <bool A_BF16>
__global__ __launch_bounds__(256) void k_gemm_tc(const float* __restrict__ Xf,
                                                 const unsigned short* __restrict__ Xh,
                                                 int wbase, int M, int K) {
    __shared__ __align__(16) unsigned As2[16 * 137];
    __shared__ __align__(16) unsigned Bs2[16 * 392];
    const int tid = threadIdx.x;
    const int wid = tid >> 5;
    const int lane = tid & 31;
    const int wm = (wid & 3) * 32;
    const int wn = wid >> 2;           // 0 or 1
    const int r = lane >> 2;
    const int c = lane & 3;
    const int rowBase = blockIdx.x * 128;

    float acc[2][10][4];
#pragma unroll
    for (int mt = 0; mt < 2; mt++)
#pragma unroll
        for (int nt = 0; nt < 10; nt++)
#pragma unroll
            for (int i = 0; i < 4; i++) acc[mt][nt][i] = 0.f;

    for (int k0 = 0; k0 < K; k0 += 32) {
        // ---- A tile fill ----
        if (A_BF16) {
            const unsigned* Xrow = reinterpret_cast<const unsigned*>(Xh);
#pragma unroll
            for (int i = 0; i < 8; i++) {
                int idx = tid + i * 256;
                int u = idx & 15;
                int row = idx >> 4;
                int gr = rowBase + row;
                unsigned v = 0u;
                if (gr < M) v = Xrow[(size_t)gr * (HID / 2) + (k0 >> 1) + u];
                As2[u * 137 + row] = v;
            }
        } else {
#pragma unroll
            for (int i = 0; i < 8; i++) {
                int idx = tid + i * 256;
                int u = idx & 15;
                int row = idx >> 4;
                int gr = rowBase + row;
                float2 v = make_float2(0.f, 0.f);
                if (gr < M) v = *reinterpret_cast<const float2*>(Xf + (size_t)gr * K + k0 + 2 * u);
                As2[u * 137 + row] = bfpack(v.x, v.y);
            }
        }
        // ---- B tile fill: straight copy of precomputed tile ----
        {
            const uint4* wsrc = reinterpret_cast<const uint4*>(g_wbuf + wbase + (k0 >> 5) * 6272);
            uint4* bdst = reinterpret_cast<uint4*>(Bs2);
#pragma unroll
            for (int i = 0; i < 7; i++) {
                int idx = tid + i * 256;       // need < 1568
                if (idx < 1568) bdst[idx] = wsrc[idx];
            }
        }
        __syncthreads();

        // ---- compute: 2 k-steps of 16 ----
#pragma unroll
        for (int ks = 0; ks < 2; ks++) {
            int kb = ks * 8;
            unsigned a[2][4];
#pragma unroll
            for (int mt = 0; mt < 2; mt++) {
                int rb = wm + mt * 16 + r;
                a[mt][0] = As2[(kb + c) * 137 + rb];
                a[mt][1] = As2[(kb + c) * 137 + rb + 8];
                a[mt][2] = As2[(kb + c + 4) * 137 + rb];
                a[mt][3] = As2[(kb + c + 4) * 137 + rb + 8];
            }
            const unsigned* b0base = &Bs2[(kb + c) * 392 + r * 48 + wn * 12];
            const unsigned* b1base = &Bs2[(kb + c + 4) * 392 + r * 48 + wn * 12];
#pragma unroll
            for (int pass = 0; pass < 2; pass++) {
                int off = pass * 24;
                uint4 p0 = *reinterpret_cast<const uint4*>(b0base + off);
                uint4 q0 = *reinterpret_cast<const uint4*>(b1base + off);
                mma_bf16(acc[0][0], a[0], p0.x, q0.x);
                mma_bf16(acc[1][0], a[1], p0.x, q0.x);
                mma_bf16(acc[0][1], a[0], p0.y, q0.y);
                mma_bf16(acc[1][1], a[1], p0.y, q0.y);
                mma_bf16(acc[0][2], a[0], p0.z, q0.z);
                mma_bf16(acc[1][2], a[1], p0.z, q0.z);
                mma_bf16(acc[0][3], a[0], p0.w, q0.w);
                mma_bf16(acc[1][3], a[1], p0.w, q0.w);
                uint4 p1 = *reinterpret_cast<const uint4*>(b0base + off + 4);
                uint4 q1 = *reinterpret_cast<const uint4*>(b1base + off + 4);
                mma_bf16(acc[0][4], a[0], p1.x, q1.x);
                mma_bf16(acc[1][4], a[1], p1.x, q1.x);
                mma_bf16(acc[0][5], a[0], p1.y, q1.y);
                mma_bf16(acc[1][5], a[1], p1.y, q1.y);
                mma_bf16(acc[0][6], a[0], p1.z, q1.z);
                mma_bf16(acc[1][6], a[1], p1.z, q1.z);
                mma_bf16(acc[0][7], a[0], p1.w, q1.w);
                mma_bf16(acc[1][7], a[1], p1.w, q1.w);
                uint2 p2 = *reinterpret_cast<const uint2*>(b0base + off + 8);
                uint2 q2 = *reinterpret_cast<const uint2*>(b1base + off + 8);
                mma_bf16(acc[0][8], a[0], p2.x, q2.x);
                mma_bf16(acc[1][8], a[1], p2.x, q2.x);
                mma_bf16(acc[0][9], a[0], p2.y, q2.y);
                mma_bf16(acc[1][9], a[1], p2.y, q2.y);
            }
        }
        __syncthreads();
    }

    // ---- epilogue: scale by inv[row], pack bf16, store ----
#pragma unroll
    for (int mt = 0; mt < 2; mt++) {
        int row0 = rowBase + wm + mt * 16 + r;
        int row1 = row0 + 8;
        float s0 = (row0 < M) ? g_inv[row0] : 0.f;
        float s1 = (row1 < M) ? g_inv[row1] : 0.f;
#pragma unroll
        for (int nt = 0; nt < 10; nt++) {
            int col = wn * 80 + nt * 8 + 2 * c;
            if (row0 < M)
                *reinterpret_cast<unsigned*>(g_hs + (size_t)row0 * HID + col) =
                    bfpack(acc[mt][nt][0] * s0, acc[mt][nt][1] * s0);
            if (row1 < M)
                *reinterpret_cast<unsigned*>(g_hs + (size_t)row1 * HID + col) =
                    bfpack(acc[mt][nt][2] * s1, acc[mt][nt][3] * s1);
        }
    }
}

// ---------------- Aggregate + bias + BN + ReLU (bf16 rows, fp32 accum) ----------------
__global__ __launch_bounds__(256) void k_agg(const float* __restrict__ bias,
                                             const float* __restrict__ gam,
                                             const float* __restrict__ bet,
                                             const float* __restrict__ mean,
                                             const float* __restrict__ var) {
    int d = (blockIdx.x * blockDim.x + threadIdx.x) >> 5;
    int lane = threadIdx.x & 31;
    if (d >= NN) return;
    bool tail = lane < 16;

    const unsigned short* hr = g_hs + (size_t)d * HID;

    float a0, a1, a2, a3, t0 = 0.f, t1 = 0.f;
    {
        uint2 v = *reinterpret_cast<const uint2*>(hr + 4 * lane);
        a0 = bflo(v.x); a1 = bfhi(v.x); a2 = bflo(v.y); a3 = bfhi(v.y);
        if (tail) {
            unsigned u = *reinterpret_cast<const unsigned*>(hr + 128 + 2 * lane);
            t0 = bflo(u); t1 = bfhi(u);
        }
    }

    int c = 4 * lane;
    int ct = 128 + 2 * lane;
    float idv = g_inv[d];
    float A0 = gam[c]     * rsqrtf(var[c]     + BN_EPS);
    float A1 = gam[c + 1] * rsqrtf(var[c + 1] + BN_EPS);
    float A2 = gam[c + 2] * rsqrtf(var[c + 2] + BN_EPS);
    float A3 = gam[c + 3] * rsqrtf(var[c + 3] + BN_EPS);
    float Q0 = (bias[c]     - mean[c])     * A0 + bet[c];
    float Q1 = (bias[c + 1] - mean[c + 1]) * A1 + bet[c + 1];
    float Q2 = (bias[c + 2] - mean[c + 2]) * A2 + bet[c + 2];
    float Q3 = (bias[c + 3] - mean[c + 3]) * A3 + bet[c + 3];
    float A4 = 0.f, A5 = 0.f, Q4 = 0.f, Q5 = 0.f;
    if (tail) {
        A4 = gam[ct]     * rsqrtf(var[ct]     + BN_EPS);
        A5 = gam[ct + 1] * rsqrtf(var[ct + 1] + BN_EPS);
        Q4 = (bias[ct]     - mean[ct])     * A4 + bet[ct];
        Q5 = (bias[ct + 1] - mean[ct + 1]) * A5 + bet[ct + 1];
    }

    int beg = g_rowptr[d], end = g_rowptr[d + 1];
    // prefetched index double-buffer
    int myidx = 0;
    {
        int n = min(32, end - beg);
        if (lane < n) myidx = g_colidx[beg + lane];
    }
    for (int e0 = beg; e0 < end; e0 += 32) {
        int n = min(32, end - e0);
        int cur = myidx;
        int e1 = e0 + 32;
        if (e1 < end) {
            int n2 = min(32, end - e1);
            myidx = (lane < n2) ? g_colidx[e1 + lane] : 0;
        }
        for (int t = 0; t < n; t++) {
            int s = __shfl_sync(0xffffffffu, cur, t);
            const unsigned short* rr = g_hs + (size_t)s * HID;
            uint2 v = *reinterpret_cast<const uint2*>(rr + 4 * lane);
            a0 += bflo(v.x); a1 += bfhi(v.x);
            a2 += bflo(v.y); a3 += bfhi(v.y);
            if (tail) {
                unsigned u = *reinterpret_cast<const unsigned*>(rr + 128 + 2 * lane);
                t0 += bflo(u); t1 += bfhi(u);
            }
        }
    }

    unsigned short* o = g_feat + (size_t)d * HID;
    float y0 = fmaxf(fmaf(a0, idv * A0, Q0), 0.f);
    float y1 = fmaxf(fmaf(a1, idv * A1, Q1), 0.f);
    float y2 = fmaxf(fmaf(a2, idv * A2, Q2), 0.f);
    float y3 = fmaxf(fmaf(a3, idv * A3, Q3), 0.f);
    uint2 ov;
    ov.x = bfpack(y0, y1);
    ov.y = bfpack(y2, y3);
    *reinterpret_cast<uint2*>(o + 4 * lane) = ov;
    if (tail) {
        float y4 = fmaxf(fmaf(t0, idv * A4, Q4), 0.f);
        float y5 = fmaxf(fmaf(t1, idv * A5, Q5), 0.f);
        *reinterpret_cast<unsigned*>(o + 128 + 2 * lane) = bfpack(y4, y5);
    }
}

// ---------------- mean pool per graph ----------------
__global__ void k_pool() {   // grid: NG blocks x 80 threads (2 cols/thread)
    int g = blockIdx.x;
    int j = threadIdx.x;
    int s0 = g_goff[g];
    int cnt = g_goff[g + 1] - s0;
    float sx = 0.f, sy = 0.f;
    for (int i = 0; i < cnt; i++) {
        unsigned u = *reinterpret_cast<const unsigned*>(g_feat + (size_t)(s0 + i) * HID + 2 * j);
        sx += bflo(u); sy += bfhi(u);
    }
    float invc = 1.f / fmaxf((float)cnt, 1.f);
    g_pooled[g * HID + 2 * j] = sx * invc;
    g_pooled[g * HID + 2 * j + 1] = sy * invc;
}

// ---------------- MLP head ----------------
__global__ void k_head(const float* __restrict__ Wc1, const float* __restrict__ bc1,
                       const float* __restrict__ Wc2, const float* __restrict__ bc2,
                       float* __restrict__ out) {   // grid: NG blocks x 80 threads
    __shared__ float p[HID];
    __shared__ float z[80];
    int g = blockIdx.x;
    int j = threadIdx.x;
    p[j] = g_pooled[g * HID + j];
    p[j + 80] = g_pooled[g * HID + j + 80];
    __syncthreads();
    float s = bc1[j];
    for (int i = 0; i < HID; i++) s = fmaf(p[i], Wc1[i * 80 + j], s);
    z[j] = fmaxf(s, 0.f);
    __syncthreads();
    if (j < NC) {
        float o = bc2[j];
        for (int i = 0; i < 80; i++) o = fmaf(z[i], Wc2[i * NC + j], o);
        out[g * NC + j] = o;
    }
}

// ---------------- launch ----------------
extern "C" void kernel_launch(void* const* d_in, const int* in_sizes, int n_in,
                              void* d_out, int out_size) {
    const float* x   = (const float*)d_in[0];
    const int* ei    = (const int*)d_in[1];
    const int* batch = (const int*)d_in[2];
    const float* W1  = (const float*)d_in[3];
    const float* b1  = (const float*)d_in[4];
    const float* W2  = (const float*)d_in[5];
    const float* b2  = (const float*)d_in[6];
    const float* W3  = (const float*)d_in[7];
    const float* b3  = (const float*)d_in[8];
    const float* g1  = (const float*)d_in[9];
    const float* be1 = (const float*)d_in[10];
    const float* m1  = (const float*)d_in[11];
    const float* v1  = (const float*)d_in[12];
    const float* g2  = (const float*)d_in[13];
    const float* be2 = (const float*)d_in[14];
    const float* m2  = (const float*)d_in[15];
    const float* v2  = (const float*)d_in[16];
    const float* g3  = (const float*)d_in[17];
    const float* be3 = (const float*)d_in[18];
    const float* m3  = (const float*)d_in[19];
    const float* v3  = (const float*)d_in[20];
    const float* Wc1 = (const float*)d_in[21];
    const float* bc1 = (const float*)d_in[22];
    const float* Wc2 = (const float*)d_in[23];
    const float* bc2 = (const float*)d_in[24];
    const int* src = ei;
    const int* dst = ei + NE;
    float* out = (float*)d_out;

    unsigned short* feat_ptr = nullptr;
    cudaGetSymbolAddress((void**)&feat_ptr, g_feat);

    const int gemm_blocks = (NN + 127) / 128;
    const int agg_blocks = (NN + 7) / 8;

    // ---- build + weight prep ----
    k_wprep<<<140, 256>>>(W1, W2, W3);
    k_zero<<<(NN + 255) / 256, 256>>>();
    k_count2<<<2048, 256>>>(dst, batch);
    k_scanall<<<TILES, 512>>>();
    k_scatter<<<2048, 256>>>(src, dst);
    k_gemm_tc<false><<<gemm_blocks, 256>>>(x, nullptr, 0, NN, FIN);    // layer-1 GEMM

    // layer 1 aggregate
    k_agg<<<agg_blocks, 256>>>(b1, g1, be1, m1, v1);
    // layer 2
    k_gemm_tc<true><<<gemm_blocks, 256>>>(nullptr, feat_ptr, 25088, NN, HID);
    k_agg<<<agg_blocks, 256>>>(b2, g2, be2, m2, v2);
    // layer 3
    k_gemm_tc<true><<<gemm_blocks, 256>>>(nullptr, feat_ptr, 56448, NN, HID);
    k_agg<<<agg_blocks, 256>>>(b3, g3, be3, m3, v3);

    // pool + head
    k_pool<<<NG, 80>>>();
    k_head<<<NG, 80>>>(Wc1, bc1, Wc2, bc2, out);
}

// round 10
// speedup vs baseline: 2.0461x; 1.0343x over previous
#include <cuda_runtime.h>
#include <math.h>

#define NN 50000
#define NE 1600000
#define FIN 128
#define HID 160
#define NG 512
#define NC 2
#define BN_EPS 1e-5f
#define TILES 98          // ceil(NN/512)

// ---------------- scratch (static __device__, no allocs) ----------------
__device__ __align__(16) unsigned short g_hs[NN * HID];    // bf16 scaled linear output
__device__ __align__(16) unsigned short g_feat[NN * HID];  // bf16 layer output features
__device__ float g_inv[NN];                                // 1/sqrt(deg)
__device__ int   g_indeg[NN];
__device__ int   g_rowptr[NN + 1];
__device__ int   g_cursor[NN];
__device__ int   g_colidx[NE];
__device__ int   g_tileagg[TILES];
__device__ int   g_tileflag[TILES];
__device__ int   g_gcnt[NG];
__device__ int   g_goff[NG + 1];
// packed hi/lo bf16x2 weight tiles, smem-tile layout: [ktile][k2(16)][j(8)][slot(48)]
// L1: 4 ktiles @0, L2: 5 @25088, L3: 5 @56448
__device__ __align__(16) unsigned g_wbuf[87808];

// ---------------- stream/event resources (created once, pre-checkpoint) ----------------
static cudaStream_t g_s1;
static cudaEvent_t g_evC, g_evG1;
namespace {
struct ResInit {
    ResInit() {
        cudaStreamCreateWithFlags(&g_s1, cudaStreamNonBlocking);
        cudaEventCreateWithFlags(&g_evC, cudaEventDisableTiming);
        cudaEventCreateWithFlags(&g_evG1, cudaEventDisableTiming);
    }
};
ResInit g_resinit;
}

// ---------------- bf16 helpers (ALU-only unpack) ----------------
__device__ __forceinline__ float bflo(unsigned u) { return __uint_as_float(u << 16); }
__device__ __forceinline__ float bfhi(unsigned u) { return __uint_as_float(u & 0xffff0000u); }
__device__ __forceinline__ unsigned bfpack(float lo, float hi) {
    unsigned r;
    asm("cvt.rn.bf16x2.f32 %0, %1, %2;" : "=r"(r) : "f"(hi), "f"(lo));
    return r;
}

__device__ __forceinline__ void mma_bf16(float* d, const unsigned* a, unsigned b0, unsigned b1) {
    asm("mma.sync.aligned.m16n8k16.row.col.f32.bf16.bf16.f32 "
        "{%0,%1,%2,%3}, {%4,%5,%6,%7}, {%8,%9}, {%0,%1,%2,%3};"
        : "+f"(d[0]), "+f"(d[1]), "+f"(d[2]), "+f"(d[3])
        : "r"(a[0]), "r"(a[1]), "r"(a[2]), "r"(a[3]), "r"(b0), "r"(b1));
}

// ---------------- weight prep + counter zeroing (merged) ----------------
__global__ void k_wprep_zero(const float* __restrict__ W1, const float* __restrict__ W2,
                             const float* __restrict__ W3) {
    int idx = blockIdx.x * blockDim.x + threadIdx.x;
    if (idx < NN) g_indeg[idx] = 0;
    if (idx < NG) g_gcnt[idx] = 0;
    if (idx < TILES) g_tileflag[idx] = 0;
    if (idx < 35840) {
        const float* W;
        int base, rel;
        if (idx < 10240)      { W = W1; base = 0;     rel = idx; }
        else if (idx < 23040) { W = W2; base = 25088; rel = idx - 10240; }
        else                  { W = W3; base = 56448; rel = idx - 23040; }
        int cc = rel % 160;
        int t = rel / 160;
        int k2 = t & 15;
        int kt = t >> 4;
        int row = kt * 32 + 2 * k2;
        float w0 = W[(size_t)row * HID + cc];
        float w1 = W[(size_t)(row + 1) * HID + cc];
        unsigned hp = bfpack(w0, w1);
        float h0 = bflo(hp), h1 = bfhi(hp);
        unsigned lp = bfpack(w0 - h0, w1 - h1);
        int j = cc & 7;
        int tile = cc >> 3;
        int slot = (tile >= 10) ? (tile + 2) : tile;
        unsigned* dstp = g_wbuf + base + kt * 6272 + k2 * 392 + j * 48;
        dstp[slot] = hp;
        dstp[slot + 24] = lp;
    }
}

__global__ void k_count2(const int* __restrict__ dst, const int* __restrict__ batch) {
    int stride = gridDim.x * blockDim.x;
    int t0 = blockIdx.x * blockDim.x + threadIdx.x;
    for (int e = t0; e < NE; e += stride)
        atomicAdd(&g_indeg[dst[e]], 1);
    for (int i = t0; i < NN; i += stride)
        atomicAdd(&g_gcnt[batch[i]], 1);
}

// inv only (runs on side stream; feeds gemm1)
__global__ void k_inv() {
    int i = blockIdx.x * blockDim.x + threadIdx.x;
    if (i < NN) g_inv[i] = rsqrtf((float)g_indeg[i] + 1.0f);
}

// single-pass scan: 98 tiles, immediate aggregate publish + full lookback.
// also the graph-offset scan in the last tile.
__global__ void k_scanall() {
    __shared__ int sh[512];
    __shared__ int s_sum;
    int bid = blockIdx.x, tid = threadIdx.x;
    int i = bid * 512 + tid;
    int v = (i < NN) ? g_indeg[i] : 0;
    sh[tid] = v;
    __syncthreads();
    for (int off = 1; off < 512; off <<= 1) {
        int t = (tid >= off) ? sh[tid - off] : 0;
        __syncthreads();
        sh[tid] += t;
        __syncthreads();
    }
    if (tid == 0) s_sum = 0;
    if (tid == 511) {
        g_tileagg[bid] = sh[511];
        __threadfence();
        g_tileflag[bid] = 1;
    }
    __syncthreads();
    volatile int* vflag = (volatile int*)g_tileflag;
    volatile int* vagg = (volatile int*)g_tileagg;
    int prev = 0;
    for (int t = tid; t < bid; t += 512) {
        while (vflag[t] == 0) {}
        prev += vagg[t];
    }
    if (prev) atomicAdd(&s_sum, prev);
    __syncthreads();
    int excl = sh[tid] - v + s_sum;
    if (i < NN) {
        g_rowptr[i] = excl;
        g_cursor[i] = excl;
    }
    if (bid == 0 && tid == 0) g_rowptr[NN] = NE;
    if (bid == TILES - 1) {
        __syncthreads();
        int vg = g_gcnt[tid];
        sh[tid] = vg;
        __syncthreads();
        for (int off = 1; off < 512; off <<= 1) {
            int t = (tid >= off) ? sh[tid - off] : 0;
            __syncthreads();
            sh[tid] += t;
            __syncthreads();
        }
        g_goff[tid] = sh[tid] - vg;
        if (tid == 511) g_goff[NG] = sh[511];
    }
}

__global__ void k_scatter(const int* __restrict__ src, const int* __restrict__ dst) {
    for (int e = blockIdx.x * blockDim.x + threadIdx.x; e < NE; e += gridDim.x * blockDim.x) {
        int p = atomicAdd(&g_cursor[dst[e]], 1);
        g_colidx[p] = src[e];
    }
}

// ---------------- tensor-core GEMM: g_hs = bf16( (X @ W) * inv[row] ) ----------------
template <bool A_BF16>
__global__ __launch_bounds__(256) void k_gemm_tc(const float* __restrict__ Xf,
                                                 const unsigned short* __restrict__ Xh,
                                                 int wbase, int M, int K) {
    __shared__ __align__(16) unsigned As2[16 * 137];
    __shared__ __align__(16) unsigned Bs2[16 * 392];
    const int tid = threadIdx.x;
    const int wid = tid >> 5;
    const int lane = tid & 31;
    const int wm = (wid & 3) * 32;
    const int wn = wid >> 2;
    const int r = lane >> 2;
    const int c = lane & 3;
    const int rowBase = blockIdx.x * 128;

    float acc[2][10][4];
#pragma unroll
    for (int mt = 0; mt < 2; mt++)
#pragma unroll
        for (int nt = 0; nt < 10; nt++)
#pragma unroll
            for (int i = 0; i < 4; i++) acc[mt][nt][i] = 0.f;

    for (int k0 = 0; k0 < K; k0 += 32) {
        if (A_BF16) {
            const unsigned* Xrow = reinterpret_cast<const unsigned*>(Xh);
#pragma unroll
            for (int i = 0; i < 8; i++) {
                int idx = tid + i * 256;
                int u = idx & 15;
                int row = idx >> 4;
                int gr = rowBase + row;
                unsigned v = 0u;
                if (gr < M) v = Xrow[(size_t)gr * (HID / 2) + (k0 >> 1) + u];
                As2[u * 137 + row] = v;
            }
        } else {
#pragma unroll
            for (int i = 0; i < 8; i++) {
                int idx = tid + i * 256;
                int u = idx & 15;
                int row = idx >> 4;
                int gr = rowBase + row;
                float2 v = make_float2(0.f, 0.f);
                if (gr < M) v = *reinterpret_cast<const float2*>(Xf + (size_t)gr * K + k0 + 2 * u);
                As2[u * 137 + row] = bfpack(v.x, v.y);
            }
        }
        {
            const uint4* wsrc = reinterpret_cast<const uint4*>(g_wbuf + wbase + (k0 >> 5) * 6272);
            uint4* bdst = reinterpret_cast<uint4*>(Bs2);
#pragma unroll
            for (int i = 0; i < 7; i++) {
                int idx = tid + i * 256;
                if (idx < 1568) bdst[idx] = wsrc[idx];
            }
        }
        __syncthreads();

#pragma unroll
        for (int ks = 0; ks < 2; ks++) {
            int kb = ks * 8;
            unsigned a[2][4];
#pragma unroll
            for (int mt = 0; mt < 2; mt++) {
                int rb = wm + mt * 16 + r;
                a[mt][0] = As2[(kb + c) * 137 + rb];
                a[mt][1] = As2[(kb + c) * 137 + rb + 8];
                a[mt][2] = As2[(kb + c + 4) * 137 + rb];
                a[mt][3] = As2[(kb + c + 4) * 137 + rb + 8];
            }
            const unsigned* b0base = &Bs2[(kb + c) * 392 + r * 48 + wn * 12];
            const unsigned* b1base = &Bs2[(kb + c + 4) * 392 + r * 48 + wn * 12];
#pragma unroll
            for (int pass = 0; pass < 2; pass++) {
                int off = pass * 24;
                uint4 p0 = *reinterpret_cast<const uint4*>(b0base + off);
                uint4 q0 = *reinterpret_cast<const uint4*>(b1base + off);
                mma_bf16(acc[0][0], a[0], p0.x, q0.x);
                mma_bf16(acc[1][0], a[1], p0.x, q0.x);
                mma_bf16(acc[0][1], a[0], p0.y, q0.y);
                mma_bf16(acc[1][1], a[1], p0.y, q0.y);
                mma_bf16(acc[0][2], a[0], p0.z, q0.z);
                mma_bf16(acc[1][2], a[1], p0.z, q0.z);
                mma_bf16(acc[0][3], a[0], p0.w, q0.w);
                mma_bf16(acc[1][3], a[1], p0.w, q0.w);
                uint4 p1 = *reinterpret_cast<const uint4*>(b0base + off + 4);
                uint4 q1 = *reinterpret_cast<const uint4*>(b1base + off + 4);
                mma_bf16(acc[0][4], a[0], p1.x, q1.x);
                mma_bf16(acc[1][4], a[1], p1.x, q1.x);
                mma_bf16(acc[0][5], a[0], p1.y, q1.y);
                mma_bf16(acc[1][5], a[1], p1.y, q1.y);
                mma_bf16(acc[0][6], a[0], p1.z, q1.z);
                mma_bf16(acc[1][6], a[1], p1.z, q1.z);
                mma_bf16(acc[0][7], a[0], p1.w, q1.w);
                mma_bf16(acc[1][7], a[1], p1.w, q1.w);
                uint2 p2 = *reinterpret_cast<const uint2*>(b0base + off + 8);
                uint2 q2 = *reinterpret_cast<const uint2*>(b1base + off + 8);
                mma_bf16(acc[0][8], a[0], p2.x, q2.x);
                mma_bf16(acc[1][8], a[1], p2.x, q2.x);
                mma_bf16(acc[0][9], a[0], p2.y, q2.y);
                mma_bf16(acc[1][9], a[1], p2.y, q2.y);
            }
        }
        __syncthreads();
    }

#pragma unroll
    for (int mt = 0; mt < 2; mt++) {
        int row0 = rowBase + wm + mt * 16 + r;
        int row1 = row0 + 8;
        float s0 = (row0 < M) ? g_inv[row0] : 0.f;
        float s1 = (row1 < M) ? g_inv[row1] : 0.f;
#pragma unroll
        for (int nt = 0; nt < 10; nt++) {
            int col = wn * 80 + nt * 8 + 2 * c;
            if (row0 < M)
                *reinterpret_cast<unsigned*>(g_hs + (size_t)row0 * HID + col) =
                    bfpack(acc[mt][nt][0] * s0, acc[mt][nt][1] * s0);
            if (row1 < M)
                *reinterpret_cast<unsigned*>(g_hs + (size_t)row1 * HID + col) =
                    bfpack(acc[mt][nt][2] * s1, acc[mt][nt][3] * s1);
        }
    }
}

// ---------------- Aggregate + bias + BN + ReLU (bf16 rows, fp32 accum) ----------------
__global__ __launch_bounds__(256) void k_agg(const float* __restrict__ bias,
                                             const float* __restrict__ gam,
                                             const float* __restrict__ bet,
                                             const float* __restrict__ mean,
                                             const float* __restrict__ var) {
    int d = (blockIdx.x * blockDim.x + threadIdx.x) >> 5;
    int lane = threadIdx.x & 31;
    if (d >= NN) return;
    bool tail = lane < 16;

    const unsigned short* hr = g_hs + (size_t)d * HID;

    float a0, a1, a2, a3, t0 = 0.f, t1 = 0.f;
    {
        uint2 v = *reinterpret_cast<const uint2*>(hr + 4 * lane);
        a0 = bflo(v.x); a1 = bfhi(v.x); a2 = bflo(v.y); a3 = bfhi(v.y);
        if (tail) {
            unsigned u = *reinterpret_cast<const unsigned*>(hr + 128 + 2 * lane);
            t0 = bflo(u); t1 = bfhi(u);
        }
    }

    int c = 4 * lane;
    int ct = 128 + 2 * lane;
    float idv = g_inv[d];
    float A0 = gam[c]     * rsqrtf(var[c]     + BN_EPS);
    float A1 = gam[c + 1] * rsqrtf(var[c + 1] + BN_EPS);
    float A2 = gam[c + 2] * rsqrtf(var[c + 2] + BN_EPS);
    float A3 = gam[c + 3] * rsqrtf(var[c + 3] + BN_EPS);
    float Q0 = (bias[c]     - mean[c])     * A0 + bet[c];
    float Q1 = (bias[c + 1] - mean[c + 1]) * A1 + bet[c + 1];
    float Q2 = (bias[c + 2] - mean[c + 2]) * A2 + bet[c + 2];
    float Q3 = (bias[c + 3] - mean[c + 3]) * A3 + bet[c + 3];
    float A4 = 0.f, A5 = 0.f, Q4 = 0.f, Q5 = 0.f;
    if (tail) {
        A4 = gam[ct]     * rsqrtf(var[ct]     + BN_EPS);
        A5 = gam[ct + 1] * rsqrtf(var[ct + 1] + BN_EPS);
        Q4 = (bias[ct]     - mean[ct])     * A4 + bet[ct];
        Q5 = (bias[ct + 1] - mean[ct + 1]) * A5 + bet[ct + 1];
    }

    int beg = g_rowptr[d], end = g_rowptr[d + 1];
    int myidx = 0;
    {
        int n = min(32, end - beg);
        if (lane < n) myidx = g_colidx[beg + lane];
    }
    for (int e0 = beg; e0 < end; e0 += 32) {
        int n = min(32, end - e0);
        int cur = myidx;
        int e1 = e0 + 32;
        if (e1 < end) {
            int n2 = min(32, end - e1);
            myidx = (lane < n2) ? g_colidx[e1 + lane] : 0;
        }
        for (int t = 0; t < n; t++) {
            int s = __shfl_sync(0xffffffffu, cur, t);
            const unsigned short* rr = g_hs + (size_t)s * HID;
            uint2 v = *reinterpret_cast<const uint2*>(rr + 4 * lane);
            a0 += bflo(v.x); a1 += bfhi(v.x);
            a2 += bflo(v.y); a3 += bfhi(v.y);
            if (tail) {
                unsigned u = *reinterpret_cast<const unsigned*>(rr + 128 + 2 * lane);
                t0 += bflo(u); t1 += bfhi(u);
            }
        }
    }

    unsigned short* o = g_feat + (size_t)d * HID;
    float y0 = fmaxf(fmaf(a0, idv * A0, Q0), 0.f);
    float y1 = fmaxf(fmaf(a1, idv * A1, Q1), 0.f);
    float y2 = fmaxf(fmaf(a2, idv * A2, Q2), 0.f);
    float y3 = fmaxf(fmaf(a3, idv * A3, Q3), 0.f);
    uint2 ov;
    ov.x = bfpack(y0, y1);
    ov.y = bfpack(y2, y3);
    *reinterpret_cast<uint2*>(o + 4 * lane) = ov;
    if (tail) {
        float y4 = fmaxf(fmaf(t0, idv * A4, Q4), 0.f);
        float y5 = fmaxf(fmaf(t1, idv * A5, Q5), 0.f);
        *reinterpret_cast<unsigned*>(o + 128 + 2 * lane) = bfpack(y4, y5);
    }
}

// ---------------- fused mean pool + MLP head ----------------
__global__ void k_poolhead(const float* __restrict__ Wc1, const float* __restrict__ bc1,
                           const float* __restrict__ Wc2, const float* __restrict__ bc2,
                           float* __restrict__ out) {   // grid: NG blocks x 80 threads
    __shared__ float p[HID];
    __shared__ float z[80];
    int g = blockIdx.x;
    int j = threadIdx.x;
    int s0 = g_goff[g];
    int cnt = g_goff[g + 1] - s0;
    float sx = 0.f, sy = 0.f;
    for (int i = 0; i < cnt; i++) {
        unsigned u = *reinterpret_cast<const unsigned*>(g_feat + (size_t)(s0 + i) * HID + 2 * j);
        sx += bflo(u); sy += bfhi(u);
    }
    float invc = 1.f / fmaxf((float)cnt, 1.f);
    p[2 * j] = sx * invc;
    p[2 * j + 1] = sy * invc;
    __syncthreads();
    float s = bc1[j];
    for (int i = 0; i < HID; i++) s = fmaf(p[i], Wc1[i * 80 + j], s);
    z[j] = fmaxf(s, 0.f);
    __syncthreads();
    if (j < NC) {
        float o = bc2[j];
        for (int i = 0; i < 80; i++) o = fmaf(z[i], Wc2[i * NC + j], o);
        out[g * NC + j] = o;
    }
}

// ---------------- launch ----------------
extern "C" void kernel_launch(void* const* d_in, const int* in_sizes, int n_in,
                              void* d_out, int out_size) {
    const float* x   = (const float*)d_in[0];
    const int* ei    = (const int*)d_in[1];
    const int* batch = (const int*)d_in[2];
    const float* W1  = (const float*)d_in[3];
    const float* b1  = (const float*)d_in[4];
    const float* W2  = (const float*)d_in[5];
    const float* b2  = (const float*)d_in[6];
    const float* W3  = (const float*)d_in[7];
    const float* b3  = (const float*)d_in[8];
    const float* g1  = (const float*)d_in[9];
    const float* be1 = (const float*)d_in[10];
    const float* m1  = (const float*)d_in[11];
    const float* v1  = (const float*)d_in[12];
    const float* g2  = (const float*)d_in[13];
    const float* be2 = (const float*)d_in[14];
    const float* m2  = (const float*)d_in[15];
    const float* v2  = (const float*)d_in[16];
    const float* g3  = (const float*)d_in[17];
    const float* be3 = (const float*)d_in[18];
    const float* m3  = (const float*)d_in[19];
    const float* v3  = (const float*)d_in[20];
    const float* Wc1 = (const float*)d_in[21];
    const float* bc1 = (const float*)d_in[22];
    const float* Wc2 = (const float*)d_in[23];
    const float* bc2 = (const float*)d_in[24];
    const int* src = ei;
    const int* dst = ei + NE;
    float* out = (float*)d_out;

    unsigned short* feat_ptr = nullptr;
    cudaGetSymbolAddress((void**)&feat_ptr, g_feat);

    const int gemm_blocks = (NN + 127) / 128;
    const int agg_blocks = (NN + 7) / 8;

    // ---- main stream: build chain ----
    k_wprep_zero<<<196, 256>>>(W1, W2, W3);
    k_count2<<<2048, 256>>>(dst, batch);
    cudaEventRecord(g_evC, 0);
    k_scanall<<<TILES, 512>>>();
    k_scatter<<<2048, 256>>>(src, dst);

    // ---- side stream: inv + layer-1 GEMM (only needs indeg + wbuf) ----
    cudaStreamWaitEvent(g_s1, g_evC, 0);
    k_inv<<<196, 256, 0, g_s1>>>();
    k_gemm_tc<false><<<gemm_blocks, 256, 0, g_s1>>>(x, nullptr, 0, NN, FIN);
    cudaEventRecord(g_evG1, g_s1);
    cudaStreamWaitEvent(0, g_evG1, 0);

    // layer 1 aggregate (needs scatter + gemm1)
    k_agg<<<agg_blocks, 256>>>(b1, g1, be1, m1, v1);
    // layer 2
    k_gemm_tc<true><<<gemm_blocks, 256>>>(nullptr, feat_ptr, 25088, NN, HID);
    k_agg<<<agg_blocks, 256>>>(b2, g2, be2, m2, v2);
    // layer 3
    k_gemm_tc<true><<<gemm_blocks, 256>>>(nullptr, feat_ptr, 56448, NN, HID);
    k_agg<<<agg_blocks, 256>>>(b3, g3, be3, m3, v3);

    // fused pool + head
    k_poolhead<<<NG, 80>>>(Wc1, bc1, Wc2, bc2, out);
}